// round 6
// baseline (speedup 1.0000x reference)
#include <cuda_runtime.h>
#include <cuda_fp16.h>
#include <math.h>
#include <stdint.h>

#define B 2
#define L 2048
#define DIMM 1024
#define H 16
#define DH 64
#define BH (B*H)      // 32
#define TOK (B*L)     // 4096

// ---------------- scratch ----------------
__device__ float g_qk[BH*L*DH];
__device__ float g_v [BH*L*DH];
__device__ float g_dot[BH*L];
__device__ float g_norm2[BH*L];
__device__ unsigned int g_maxn2[BH];
__device__ unsigned char g_hq[BH*L];
__device__ unsigned char g_hk[BH*L];

__device__ __forceinline__ uint32_t f2tf(float f){
    uint32_t r; asm("cvt.rna.tf32.f32 %0, %1;" : "=r"(r) : "f"(f)); return r;
}
__device__ __forceinline__ uint32_t f22h2(float a, float b){
    __half2 h = __floats2half2_rn(a, b);
    return *(uint32_t*)&h;
}

__device__ __forceinline__ void mma_tf32(float c[4],
    uint32_t a0, uint32_t a1, uint32_t a2, uint32_t a3,
    uint32_t b0, uint32_t b1)
{
    asm("mma.sync.aligned.m16n8k8.row.col.f32.tf32.tf32.f32 "
        "{%0,%1,%2,%3}, {%4,%5,%6,%7}, {%8,%9}, {%0,%1,%2,%3};"
        : "+f"(c[0]), "+f"(c[1]), "+f"(c[2]), "+f"(c[3])
        : "r"(a0), "r"(a1), "r"(a2), "r"(a3), "r"(b0), "r"(b1));
}
__device__ __forceinline__ void mma_f16(float c[4],
    uint32_t a0, uint32_t a1, uint32_t a2, uint32_t a3,
    uint32_t b0, uint32_t b1)
{
    asm("mma.sync.aligned.m16n8k16.row.col.f32.f16.f16.f32 "
        "{%0,%1,%2,%3}, {%4,%5,%6,%7}, {%8,%9}, {%0,%1,%2,%3};"
        : "+f"(c[0]), "+f"(c[1]), "+f"(c[2]), "+f"(c[3])
        : "r"(a0), "r"(a1), "r"(a2), "r"(a3), "r"(b0), "r"(b1));
}

// ============ tensor-core projection (tile M=128, N=64=one head, Kc=32) ============
// THREE=1: 3xTF32 qk projection with FUSED hash stage-1 in epilogue.
#define PSTR 36
#define XH_OFF 0
#define XL_OFF (128*PSTR)
#define WH_OFF (2*128*PSTR)
#define WL_OFF (WH_OFF + 64*PSTR)
#define PROJ_SM_WORDS (WL_OFF + 64*PSTR)
#define PROJ_SM_BYTES (PROJ_SM_WORDS*4)

template<bool THREE>
__global__ __launch_bounds__(256, 2)
void proj_tc_kernel(const float* __restrict__ X,
                    const float* __restrict__ W,
                    const float* __restrict__ bias,
                    const float* __restrict__ ha)
{
    extern __shared__ uint32_t psm[];
    uint32_t* XH = psm + XH_OFF;
    uint32_t* XL = psm + XL_OFF;
    uint32_t* WH = psm + WH_OFF;
    uint32_t* WL = psm + WL_OFF;

    float* out = THREE ? g_qk : g_v;

    const int m0 = blockIdx.y * 128;
    const int n0 = blockIdx.x * 64;
    const int tid = threadIdx.x;
    const int warp = tid >> 5;
    const int lane = tid & 31;
    const int gy = lane >> 2;
    const int gx = lane & 3;
    const int qr = warp * 16;

    const int fxr = tid >> 1;
    const int fxc = (tid & 1) * 16;
    const int fwr = tid >> 2;
    const int fwc = (tid & 3) * 8;

    float acc[8][4];
    #pragma unroll
    for (int nt=0;nt<8;nt++)
        #pragma unroll
        for (int c=0;c<4;c++) acc[nt][c] = 0.0f;

    const float* xp0 = &X[(size_t)(m0+fxr)*DIMM + fxc];
    const float* wp0 = &W[(size_t)(n0+fwr)*DIMM + fwc];

    for (int kk = 0; kk < DIMM; kk += 32) {
        float4 xa[4], wa[2];
        #pragma unroll
        for (int j=0;j<4;j++) xa[j] = *(const float4*)&xp0[kk + j*4];
        #pragma unroll
        for (int j=0;j<2;j++) wa[j] = *(const float4*)&wp0[kk + j*4];

        __syncthreads();

        #pragma unroll
        for (int j=0;j<4;j++){
            float v4[4] = {xa[j].x, xa[j].y, xa[j].z, xa[j].w};
            uint4 h, l;
            uint32_t* hp = &h.x; uint32_t* lp = &l.x;
            #pragma unroll
            for (int e=0;e<4;e++){
                uint32_t hi = f2tf(v4[e]);
                hp[e] = hi;
                if (THREE) lp[e] = f2tf(v4[e] - __uint_as_float(hi));
            }
            *(uint4*)&XH[fxr*PSTR + fxc + j*4] = h;
            if (THREE) *(uint4*)&XL[fxr*PSTR + fxc + j*4] = l;
        }
        #pragma unroll
        for (int j=0;j<2;j++){
            float v4[4] = {wa[j].x, wa[j].y, wa[j].z, wa[j].w};
            uint4 h, l;
            uint32_t* hp = &h.x; uint32_t* lp = &l.x;
            #pragma unroll
            for (int e=0;e<4;e++){
                uint32_t hi = f2tf(v4[e]);
                hp[e] = hi;
                if (THREE) lp[e] = f2tf(v4[e] - __uint_as_float(hi));
            }
            *(uint4*)&WH[fwr*PSTR + fwc + j*4] = h;
            if (THREE) *(uint4*)&WL[fwr*PSTR + fwc + j*4] = l;
        }
        __syncthreads();

        #pragma unroll
        for (int ks = 0; ks < 4; ks++) {
            uint32_t ah0 = XH[(qr+gy  )*PSTR + ks*8 + gx];
            uint32_t ah1 = XH[(qr+gy+8)*PSTR + ks*8 + gx];
            uint32_t ah2 = XH[(qr+gy  )*PSTR + ks*8 + gx + 4];
            uint32_t ah3 = XH[(qr+gy+8)*PSTR + ks*8 + gx + 4];
            uint32_t al0=0, al1=0, al2=0, al3=0;
            if (THREE) {
                al0 = XL[(qr+gy  )*PSTR + ks*8 + gx];
                al1 = XL[(qr+gy+8)*PSTR + ks*8 + gx];
                al2 = XL[(qr+gy  )*PSTR + ks*8 + gx + 4];
                al3 = XL[(qr+gy+8)*PSTR + ks*8 + gx + 4];
            }
            #pragma unroll
            for (int nt = 0; nt < 8; nt++) {
                uint32_t bh0 = WH[(nt*8+gy)*PSTR + ks*8 + gx];
                uint32_t bh1 = WH[(nt*8+gy)*PSTR + ks*8 + gx + 4];
                if (THREE) {
                    uint32_t bl0 = WL[(nt*8+gy)*PSTR + ks*8 + gx];
                    uint32_t bl1 = WL[(nt*8+gy)*PSTR + ks*8 + gx + 4];
                    mma_tf32(acc[nt], ah0, ah1, ah2, ah3, bl0, bl1);
                    mma_tf32(acc[nt], al0, al1, al2, al3, bh0, bh1);
                }
                mma_tf32(acc[nt], ah0, ah1, ah2, ah3, bh0, bh1);
            }
        }
    }

    const int hh = blockIdx.x;
    const int m_0 = m0 + qr + gy;
    const int m_1 = m_0 + 8;
    const int b0_ = m_0 >> 11, l0_ = m_0 & (L-1);
    const int b1_ = m_1 >> 11, l1_ = m_1 & (L-1);
    float* o0 = &out[(((size_t)(b0_*H + hh)*L + l0_)*DH)];
    float* o1 = &out[(((size_t)(b1_*H + hh)*L + l1_)*DH)];

    float dot0 = 0.f, n20 = 0.f, dot1 = 0.f, n21 = 0.f;
    #pragma unroll
    for (int nt = 0; nt < 8; nt++) {
        float bs0 = bias[hh*64 + nt*8 + 2*gx];
        float bs1 = bias[hh*64 + nt*8 + 2*gx + 1];
        float v00 = acc[nt][0] + bs0, v01 = acc[nt][1] + bs1;
        float v10 = acc[nt][2] + bs0, v11 = acc[nt][3] + bs1;
        *(float2*)&o0[nt*8 + 2*gx] = make_float2(v00, v01);
        *(float2*)&o1[nt*8 + 2*gx] = make_float2(v10, v11);
        if (THREE) {
            float a0 = ha[nt*8 + 2*gx], a1 = ha[nt*8 + 2*gx + 1];
            dot0 = fmaf(v00, a0, fmaf(v01, a1, dot0));
            dot1 = fmaf(v10, a0, fmaf(v11, a1, dot1));
            n20  = fmaf(v00, v00, fmaf(v01, v01, n20));
            n21  = fmaf(v10, v10, fmaf(v11, v11, n21));
        }
    }
    if (THREE) {
        #pragma unroll
        for (int o = 1; o <= 2; o <<= 1) {
            dot0 += __shfl_xor_sync(0xffffffffu, dot0, o);
            dot1 += __shfl_xor_sync(0xffffffffu, dot1, o);
            n20  += __shfl_xor_sync(0xffffffffu, n20, o);
            n21  += __shfl_xor_sync(0xffffffffu, n21, o);
        }
        if (gx == 0) {
            size_t gw0 = (size_t)(b0_*H + hh)*L + l0_;
            size_t gw1 = (size_t)(b1_*H + hh)*L + l1_;
            g_dot[gw0] = dot0; g_norm2[gw0] = n20;
            g_dot[gw1] = dot1; g_norm2[gw1] = n21;
            atomicMax(&g_maxn2[b0_*H + hh], __float_as_uint(n20));
            atomicMax(&g_maxn2[b1_*H + hh], __float_as_uint(n21));
        }
    }
}

// ---------------- hash ----------------
__global__ void init_maxn_kernel() {
    if (threadIdx.x < BH) g_maxn2[threadIdx.x] = 0u;
}

__global__ void hash2_kernel(const float* __restrict__ ha) {
    int t = blockIdx.x * blockDim.x + threadIdx.x;
    if (t >= BH*L) return;
    float dot = g_dot[t], n2 = g_norm2[t];
    float maxn = sqrtf(__uint_as_float(g_maxn2[t >> 11]));
    float s = 0.75f / fmaxf(maxn, 1e-12f);
    float nk2 = s*s*n2;
    float hkval = s*dot + (0.5f - nk2)*ha[DH] + (0.5f - nk2*nk2)*ha[DH+1];
    g_hq[t] = (dot   >= 0.0f) ? 1 : 0;
    g_hk[t] = (hkval >= 0.0f) ? 1 : 0;
}

// ============ fp16 tensor-core flash attention ============
// 256 thr / 8 warps, Q-tile 128, K-tile 64, mma.m16n8k16.f16, fp32 softmax/accum.
#define HSTR 72   // halves per row (64 + 8 pad) -> 36 words, conflict-free frags

#define QS_OFF 0
#define KS_OFF (128*HSTR)            // 9216
#define VT_OFF (KS_OFF + 64*HSTR)    // 13824
#define PS_OFF (VT_OFF + 64*HSTR)    // 18432
#define HK_OFF (PS_OFF + 128*HSTR)   // 27648 (half units; 4B aligned)
#define ASM_HALVES (HK_OFF + 128)
#define ASM_BYTES (ASM_HALVES*2)     // 55552

__global__ __launch_bounds__(256, 2)
void attn_kernel(float* __restrict__ out) {
    extern __shared__ __half smh[];
    __half* Qs = smh + QS_OFF;
    __half* Ks = smh + KS_OFF;
    __half* Vt = smh + VT_OFF;
    __half* Ps = smh + PS_OFF;
    float* hkf = (float*)(smh + HK_OFF);

    const int bh = blockIdx.y;
    const int q0 = blockIdx.x * 128;
    const int tid = threadIdx.x;
    const int warp = tid >> 5;
    const int lane = tid & 31;
    const int gy = lane >> 2;
    const int gx = lane & 3;
    const int qr = warp * 16;

    // ---- Q fill (fp16) ----
    {
        int r = tid >> 1, c0 = (tid & 1) * 32;
        const float* qp = &g_qk[((size_t)bh*L + q0 + r)*DH + c0];
        #pragma unroll
        for (int c4 = 0; c4 < 8; c4++) {
            float4 a = *(const float4*)&qp[c4*4];
            *(uint2*)&Qs[r*HSTR + c0 + c4*4] =
                make_uint2(f22h2(a.x, a.y), f22h2(a.z, a.w));
        }
    }

    const float fq0 = (float)g_hq[(size_t)bh*L + q0 + qr + gy];
    const float fq1 = (float)g_hq[(size_t)bh*L + q0 + qr + gy + 8];

    float O[8][4];
    #pragma unroll
    for (int nt=0;nt<8;nt++)
        #pragma unroll
        for (int c=0;c<4;c++) O[nt][c] = 0.0f;
    float m0 = -INFINITY, m1 = -INFINITY, l0 = 0.0f, l1 = 0.0f;

    const int fr = tid >> 2;           // K fill row 0..63
    const int fc = (tid & 3) * 16;
    const int vd0 = warp * 8;          // V^T fill: this warp's 8 d-rows

    for (int k0 = 0; k0 < L; k0 += 64) {
        // prefetch K (natural) and V (2 rows for transpose) into regs
        float4 kr[4];
        {
            const float* kp = &g_qk[((size_t)bh*L + k0 + fr)*DH + fc];
            #pragma unroll
            for (int c4=0;c4<4;c4++) kr[c4] = *(const float4*)&kp[c4*4];
        }
        float4 va0, va1, vb0, vb1;
        {
            const float* vp0 = &g_v[((size_t)bh*L + k0 + 2*lane)*DH + vd0];
            va0 = *(const float4*)&vp0[0];
            va1 = *(const float4*)&vp0[4];
            vb0 = *(const float4*)&vp0[DH];
            vb1 = *(const float4*)&vp0[DH+4];
        }
        unsigned char hkb = 0;
        if (tid < 64) hkb = g_hk[(size_t)bh*L + k0 + tid];

        __syncthreads();
        #pragma unroll
        for (int c4=0;c4<4;c4++)
            *(uint2*)&Ks[fr*HSTR + fc + c4*4] =
                make_uint2(f22h2(((const float*)&kr[c4])[0], ((const float*)&kr[c4])[1]),
                           f22h2(((const float*)&kr[c4])[2], ((const float*)&kr[c4])[3]));
        {
            const float* a0p = (const float*)&va0; const float* a1p = (const float*)&va1;
            const float* b0p = (const float*)&vb0; const float* b1p = (const float*)&vb1;
            #pragma unroll
            for (int e=0;e<4;e++){
                *(uint32_t*)&Vt[(vd0+e  )*HSTR + 2*lane] = f22h2(a0p[e], b0p[e]);
                *(uint32_t*)&Vt[(vd0+e+4)*HSTR + 2*lane] = f22h2(a1p[e], b1p[e]);
            }
        }
        if (tid < 64) hkf[tid] = (float)hkb;
        __syncthreads();

        // ---- S = Q @ K^T ----
        float S[8][4];
        #pragma unroll
        for (int nt=0;nt<8;nt++)
            #pragma unroll
            for (int c=0;c<4;c++) S[nt][c] = 0.0f;

        #pragma unroll
        for (int ks = 0; ks < 4; ks++) {
            uint32_t a0 = *(uint32_t*)&Qs[(qr+gy  )*HSTR + ks*16 + 2*gx];
            uint32_t a1 = *(uint32_t*)&Qs[(qr+gy+8)*HSTR + ks*16 + 2*gx];
            uint32_t a2 = *(uint32_t*)&Qs[(qr+gy  )*HSTR + ks*16 + 2*gx + 8];
            uint32_t a3 = *(uint32_t*)&Qs[(qr+gy+8)*HSTR + ks*16 + 2*gx + 8];
            #pragma unroll
            for (int nt = 0; nt < 8; nt++) {
                uint32_t b0 = *(uint32_t*)&Ks[(nt*8+gy)*HSTR + ks*16 + 2*gx];
                uint32_t b1 = *(uint32_t*)&Ks[(nt*8+gy)*HSTR + ks*16 + 2*gx + 8];
                mma_f16(S[nt], a0, a1, a2, a3, b0, b1);
            }
        }

        // ---- mask + scale; row max ----
        float mx0 = -INFINITY, mx1 = -INFINITY;
        #pragma unroll
        for (int nt = 0; nt < 8; nt++) {
            float fk0 = hkf[nt*8 + 2*gx];
            float fk1 = hkf[nt*8 + 2*gx + 1];
            S[nt][0] = fmaf(S[nt][0], 0.125f, -1e4f*fabsf(fq0 - fk0));
            S[nt][1] = fmaf(S[nt][1], 0.125f, -1e4f*fabsf(fq0 - fk1));
            S[nt][2] = fmaf(S[nt][2], 0.125f, -1e4f*fabsf(fq1 - fk0));
            S[nt][3] = fmaf(S[nt][3], 0.125f, -1e4f*fabsf(fq1 - fk1));
            mx0 = fmaxf(mx0, fmaxf(S[nt][0], S[nt][1]));
            mx1 = fmaxf(mx1, fmaxf(S[nt][2], S[nt][3]));
        }
        #pragma unroll
        for (int o = 1; o <= 2; o <<= 1) {
            mx0 = fmaxf(mx0, __shfl_xor_sync(0xffffffffu, mx0, o));
            mx1 = fmaxf(mx1, __shfl_xor_sync(0xffffffffu, mx1, o));
        }
        float mn0 = fmaxf(m0, mx0), mn1 = fmaxf(m1, mx1);
        float cr0 = __expf(m0 - mn0), cr1 = __expf(m1 - mn1);
        m0 = mn0; m1 = mn1;

        // ---- exp, row sums, stage P (fp16) ----
        float s0 = 0.0f, s1 = 0.0f;
        #pragma unroll
        for (int nt = 0; nt < 8; nt++) {
            float p0 = __expf(S[nt][0] - mn0);
            float p1 = __expf(S[nt][1] - mn0);
            float p2 = __expf(S[nt][2] - mn1);
            float p3 = __expf(S[nt][3] - mn1);
            s0 += p0 + p1; s1 += p2 + p3;
            *(uint32_t*)&Ps[(qr+gy  )*HSTR + nt*8 + 2*gx] = f22h2(p0, p1);
            *(uint32_t*)&Ps[(qr+gy+8)*HSTR + nt*8 + 2*gx] = f22h2(p2, p3);
        }
        #pragma unroll
        for (int o = 1; o <= 2; o <<= 1) {
            s0 += __shfl_xor_sync(0xffffffffu, s0, o);
            s1 += __shfl_xor_sync(0xffffffffu, s1, o);
        }
        l0 = l0*cr0 + s0;
        l1 = l1*cr1 + s1;

        #pragma unroll
        for (int nt = 0; nt < 8; nt++) {
            O[nt][0] *= cr0; O[nt][1] *= cr0;
            O[nt][2] *= cr1; O[nt][3] *= cr1;
        }
        __syncwarp();

        // ---- O += P @ V ----
        #pragma unroll
        for (int ks = 0; ks < 4; ks++) {
            uint32_t a0 = *(uint32_t*)&Ps[(qr+gy  )*HSTR + ks*16 + 2*gx];
            uint32_t a1 = *(uint32_t*)&Ps[(qr+gy+8)*HSTR + ks*16 + 2*gx];
            uint32_t a2 = *(uint32_t*)&Ps[(qr+gy  )*HSTR + ks*16 + 2*gx + 8];
            uint32_t a3 = *(uint32_t*)&Ps[(qr+gy+8)*HSTR + ks*16 + 2*gx + 8];
            #pragma unroll
            for (int nt = 0; nt < 8; nt++) {
                uint32_t b0 = *(uint32_t*)&Vt[(nt*8+gy)*HSTR + ks*16 + 2*gx];
                uint32_t b1 = *(uint32_t*)&Vt[(nt*8+gy)*HSTR + ks*16 + 2*gx + 8];
                mma_f16(O[nt], a0, a1, a2, a3, b0, b1);
            }
        }
    }

    // ---- epilogue ----
    const int bb = bh >> 4, hh = bh & 15;
    const float inv0 = 1.0f / l0, inv1 = 1.0f / l1;
    const int l_0 = q0 + qr + gy, l_1 = l_0 + 8;
    float* o0 = &out[((size_t)bb*L + l_0)*DIMM + hh*DH];
    float* o1 = &out[((size_t)bb*L + l_1)*DIMM + hh*DH];
    #pragma unroll
    for (int nt = 0; nt < 8; nt++) {
        *(float2*)&o0[nt*8 + 2*gx] = make_float2(O[nt][0]*inv0, O[nt][1]*inv0);
        *(float2*)&o1[nt*8 + 2*gx] = make_float2(O[nt][2]*inv1, O[nt][3]*inv1);
    }
}

// ---------------- launch ----------------
extern "C" void kernel_launch(void* const* d_in, const int* in_sizes, int n_in,
                              void* d_out, int out_size) {
    const float* X  = (const float*)d_in[0];
    const float* Wq = (const float*)d_in[1];
    const float* bq = (const float*)d_in[2];
    const float* Wv = (const float*)d_in[3];
    const float* bv = (const float*)d_in[4];
    const float* ha = (const float*)d_in[5];
    float* out = (float*)d_out;

    cudaFuncSetAttribute(proj_tc_kernel<true>,  cudaFuncAttributeMaxDynamicSharedMemorySize, PROJ_SM_BYTES);
    cudaFuncSetAttribute(proj_tc_kernel<false>, cudaFuncAttributeMaxDynamicSharedMemorySize, PROJ_SM_BYTES);
    cudaFuncSetAttribute(attn_kernel, cudaFuncAttributeMaxDynamicSharedMemorySize, ASM_BYTES);

    init_maxn_kernel<<<1, 32>>>();

    dim3 pg(DIMM/64, TOK/128);
    proj_tc_kernel<true ><<<pg, 256, PROJ_SM_BYTES>>>(X, Wq, bq, ha);  // qk + hash1 fused
    proj_tc_kernel<false><<<pg, 256, PROJ_SM_BYTES>>>(X, Wv, bv, ha);  // v

    hash2_kernel<<<(BH*L)/256, 256>>>(ha);

    dim3 ag(L/128, BH);
    attn_kernel<<<ag, 256, ASM_BYTES>>>(out);
}

// round 7
// speedup vs baseline: 1.1456x; 1.1456x over previous
#include <cuda_runtime.h>
#include <cuda_fp16.h>
#include <math.h>
#include <stdint.h>

#define B 2
#define L 2048
#define DIMM 1024
#define H 16
#define DH 64
#define BH (B*H)      // 32
#define TOK (B*L)     // 4096

// ---------------- scratch ----------------
__device__ float g_qk[BH*L*DH];
__device__ float g_v [BH*L*DH];
__device__ float g_dot[BH*L];
__device__ float g_norm2[BH*L];
__device__ unsigned int g_maxn2[BH];
__device__ unsigned char g_hq[BH*L];
__device__ unsigned char g_hk[BH*L];

__device__ __forceinline__ uint32_t f22h2(float a, float b){
    __half2 h = __floats2half2_rn(a, b);
    return *(uint32_t*)&h;
}
__device__ __forceinline__ uint32_t packh2(__half a, __half b){
    __half2 h = __halves2half2(a, b);
    return *(uint32_t*)&h;
}

__device__ __forceinline__ void mma_f16(float c[4],
    uint32_t a0, uint32_t a1, uint32_t a2, uint32_t a3,
    uint32_t b0, uint32_t b1)
{
    asm("mma.sync.aligned.m16n8k16.row.col.f32.f16.f16.f32 "
        "{%0,%1,%2,%3}, {%4,%5,%6,%7}, {%8,%9}, {%0,%1,%2,%3};"
        : "+f"(c[0]), "+f"(c[1]), "+f"(c[2]), "+f"(c[3])
        : "r"(a0), "r"(a1), "r"(a2), "r"(a3), "r"(b0), "r"(b1));
}

// ============ fp16 tensor-core projection (tile M=128, N=64=one head, Kc=32) ============
// SPLIT=1: qk projection, 3-term split-fp16 (error ~2^-24) + fused hash stage-1.
// SPLIT=0: v projection, single fp16 pass.
#define HPSTR 72   // halves per row (64 data + 8 pad)
#define PH_XH 0
#define PH_WH (128*HPSTR)            // 9216
#define PH_XL (PH_WH + 64*HPSTR)     // 13824
#define PH_WL (PH_XL + 128*HPSTR)    // 23040
#define PROJ_H_SPLIT_BYTES ((PH_WL + 64*HPSTR)*2)   // 55296
#define PROJ_H_PLAIN_BYTES (PH_XL*2)                // 27648

template<bool SPLIT>
__global__ __launch_bounds__(256, 2)
void proj_h_kernel(const float* __restrict__ X,
                   const float* __restrict__ W,
                   const float* __restrict__ bias,
                   const float* __restrict__ ha)
{
    extern __shared__ __half hsm[];
    __half* XH = hsm + PH_XH;
    __half* WH = hsm + PH_WH;
    __half* XL = hsm + PH_XL;
    __half* WL = hsm + PH_WL;

    float* out = SPLIT ? g_qk : g_v;

    const int m0 = blockIdx.y * 128;
    const int n0 = blockIdx.x * 64;
    const int tid = threadIdx.x;
    const int warp = tid >> 5;
    const int lane = tid & 31;
    const int gy = lane >> 2;
    const int gx = lane & 3;
    const int qr = warp * 16;

    const int fxr = tid >> 1;          // 0..127
    const int fxc = (tid & 1) * 16;
    const int fwr = tid >> 2;          // 0..63
    const int fwc = (tid & 3) * 8;

    float acc1[8][4];
    float acc2[8][4];
    #pragma unroll
    for (int nt=0;nt<8;nt++)
        #pragma unroll
        for (int c=0;c<4;c++){ acc1[nt][c] = 0.0f; acc2[nt][c] = 0.0f; }

    const float* xp0 = &X[(size_t)(m0+fxr)*DIMM + fxc];
    const float* wp0 = &W[(size_t)(n0+fwr)*DIMM + fwc];

    for (int kk = 0; kk < DIMM; kk += 32) {
        float4 xa[4], wa[2];
        #pragma unroll
        for (int j=0;j<4;j++) xa[j] = *(const float4*)&xp0[kk + j*4];
        #pragma unroll
        for (int j=0;j<2;j++) wa[j] = *(const float4*)&wp0[kk + j*4];

        __syncthreads();

        #pragma unroll
        for (int j=0;j<2;j++){   // X: 16 floats -> pairs of float4
            const float* v8 = (const float*)&xa[j*2];
            uint32_t hh[4], ll[4];
            #pragma unroll
            for (int e=0;e<4;e++){
                float x0 = v8[2*e], x1 = v8[2*e+1];
                __half h0 = __float2half_rn(x0), h1 = __float2half_rn(x1);
                hh[e] = packh2(h0, h1);
                if (SPLIT)
                    ll[e] = f22h2((x0 - __half2float(h0))*2048.0f,
                                  (x1 - __half2float(h1))*2048.0f);
            }
            *(uint4*)&XH[fxr*HPSTR + fxc + j*8] = *(uint4*)hh;
            if (SPLIT) *(uint4*)&XL[fxr*HPSTR + fxc + j*8] = *(uint4*)ll;
        }
        {
            const float* v8 = (const float*)&wa[0];
            uint32_t hh[4], ll[4];
            #pragma unroll
            for (int e=0;e<4;e++){
                float x0 = v8[2*e], x1 = v8[2*e+1];
                __half h0 = __float2half_rn(x0), h1 = __float2half_rn(x1);
                hh[e] = packh2(h0, h1);
                if (SPLIT)
                    ll[e] = f22h2((x0 - __half2float(h0))*2048.0f,
                                  (x1 - __half2float(h1))*2048.0f);
            }
            *(uint4*)&WH[fwr*HPSTR + fwc] = *(uint4*)hh;
            if (SPLIT) *(uint4*)&WL[fwr*HPSTR + fwc] = *(uint4*)ll;
        }
        __syncthreads();

        #pragma unroll
        for (int ks = 0; ks < 2; ks++) {
            uint32_t ah0 = *(uint32_t*)&XH[(qr+gy  )*HPSTR + ks*16 + 2*gx];
            uint32_t ah1 = *(uint32_t*)&XH[(qr+gy+8)*HPSTR + ks*16 + 2*gx];
            uint32_t ah2 = *(uint32_t*)&XH[(qr+gy  )*HPSTR + ks*16 + 2*gx + 8];
            uint32_t ah3 = *(uint32_t*)&XH[(qr+gy+8)*HPSTR + ks*16 + 2*gx + 8];
            uint32_t al0=0, al1=0, al2=0, al3=0;
            if (SPLIT) {
                al0 = *(uint32_t*)&XL[(qr+gy  )*HPSTR + ks*16 + 2*gx];
                al1 = *(uint32_t*)&XL[(qr+gy+8)*HPSTR + ks*16 + 2*gx];
                al2 = *(uint32_t*)&XL[(qr+gy  )*HPSTR + ks*16 + 2*gx + 8];
                al3 = *(uint32_t*)&XL[(qr+gy+8)*HPSTR + ks*16 + 2*gx + 8];
            }
            #pragma unroll
            for (int nt = 0; nt < 8; nt++) {
                uint32_t bh0 = *(uint32_t*)&WH[(nt*8+gy)*HPSTR + ks*16 + 2*gx];
                uint32_t bh1 = *(uint32_t*)&WH[(nt*8+gy)*HPSTR + ks*16 + 2*gx + 8];
                mma_f16(acc1[nt], ah0, ah1, ah2, ah3, bh0, bh1);
                if (SPLIT) {
                    uint32_t bl0 = *(uint32_t*)&WL[(nt*8+gy)*HPSTR + ks*16 + 2*gx];
                    uint32_t bl1 = *(uint32_t*)&WL[(nt*8+gy)*HPSTR + ks*16 + 2*gx + 8];
                    mma_f16(acc2[nt], ah0, ah1, ah2, ah3, bl0, bl1);
                    mma_f16(acc2[nt], al0, al1, al2, al3, bh0, bh1);
                }
            }
        }
    }

    const int hh = blockIdx.x;
    const int m_0 = m0 + qr + gy;
    const int m_1 = m_0 + 8;
    const int b0_ = m_0 >> 11, l0_ = m_0 & (L-1);
    const int b1_ = m_1 >> 11, l1_ = m_1 & (L-1);
    float* o0 = &out[(((size_t)(b0_*H + hh)*L + l0_)*DH)];
    float* o1 = &out[(((size_t)(b1_*H + hh)*L + l1_)*DH)];

    const float inv2048 = 1.0f/2048.0f;
    float dot0 = 0.f, n20 = 0.f, dot1 = 0.f, n21 = 0.f;
    #pragma unroll
    for (int nt = 0; nt < 8; nt++) {
        float bs0 = bias[hh*64 + nt*8 + 2*gx];
        float bs1 = bias[hh*64 + nt*8 + 2*gx + 1];
        float v00, v01, v10, v11;
        if (SPLIT) {
            v00 = fmaf(acc2[nt][0], inv2048, acc1[nt][0]) + bs0;
            v01 = fmaf(acc2[nt][1], inv2048, acc1[nt][1]) + bs1;
            v10 = fmaf(acc2[nt][2], inv2048, acc1[nt][2]) + bs0;
            v11 = fmaf(acc2[nt][3], inv2048, acc1[nt][3]) + bs1;
        } else {
            v00 = acc1[nt][0] + bs0; v01 = acc1[nt][1] + bs1;
            v10 = acc1[nt][2] + bs0; v11 = acc1[nt][3] + bs1;
        }
        *(float2*)&o0[nt*8 + 2*gx] = make_float2(v00, v01);
        *(float2*)&o1[nt*8 + 2*gx] = make_float2(v10, v11);
        if (SPLIT) {
            float a0 = ha[nt*8 + 2*gx], a1 = ha[nt*8 + 2*gx + 1];
            dot0 = fmaf(v00, a0, fmaf(v01, a1, dot0));
            dot1 = fmaf(v10, a0, fmaf(v11, a1, dot1));
            n20  = fmaf(v00, v00, fmaf(v01, v01, n20));
            n21  = fmaf(v10, v10, fmaf(v11, v11, n21));
        }
    }
    if (SPLIT) {
        #pragma unroll
        for (int o = 1; o <= 2; o <<= 1) {
            dot0 += __shfl_xor_sync(0xffffffffu, dot0, o);
            dot1 += __shfl_xor_sync(0xffffffffu, dot1, o);
            n20  += __shfl_xor_sync(0xffffffffu, n20, o);
            n21  += __shfl_xor_sync(0xffffffffu, n21, o);
        }
        if (gx == 0) {
            size_t gw0 = (size_t)(b0_*H + hh)*L + l0_;
            size_t gw1 = (size_t)(b1_*H + hh)*L + l1_;
            g_dot[gw0] = dot0; g_norm2[gw0] = n20;
            g_dot[gw1] = dot1; g_norm2[gw1] = n21;
            atomicMax(&g_maxn2[b0_*H + hh], __float_as_uint(n20));
            atomicMax(&g_maxn2[b1_*H + hh], __float_as_uint(n21));
        }
    }
}

// ---------------- hash ----------------
__global__ void init_maxn_kernel() {
    if (threadIdx.x < BH) g_maxn2[threadIdx.x] = 0u;
}

__global__ void hash2_kernel(const float* __restrict__ ha) {
    int t = blockIdx.x * blockDim.x + threadIdx.x;
    if (t >= BH*L) return;
    float dot = g_dot[t], n2 = g_norm2[t];
    float maxn = sqrtf(__uint_as_float(g_maxn2[t >> 11]));
    float s = 0.75f / fmaxf(maxn, 1e-12f);
    float nk2 = s*s*n2;
    float hkval = s*dot + (0.5f - nk2)*ha[DH] + (0.5f - nk2*nk2)*ha[DH+1];
    g_hq[t] = (dot   >= 0.0f) ? 1 : 0;
    g_hk[t] = (hkval >= 0.0f) ? 1 : 0;
}

// ============ fp16 tensor-core flash attention (unchanged from R5) ============
#define HSTR 72

#define QS_OFF 0
#define KS_OFF (128*HSTR)
#define VT_OFF (KS_OFF + 64*HSTR)
#define PS_OFF (VT_OFF + 64*HSTR)
#define HK_OFF (PS_OFF + 128*HSTR)
#define ASM_HALVES (HK_OFF + 128)
#define ASM_BYTES (ASM_HALVES*2)

__global__ __launch_bounds__(256, 2)
void attn_kernel(float* __restrict__ out) {
    extern __shared__ __half smh[];
    __half* Qs = smh + QS_OFF;
    __half* Ks = smh + KS_OFF;
    __half* Vt = smh + VT_OFF;
    __half* Ps = smh + PS_OFF;
    float* hkf = (float*)(smh + HK_OFF);

    const int bh = blockIdx.y;
    const int q0 = blockIdx.x * 128;
    const int tid = threadIdx.x;
    const int warp = tid >> 5;
    const int lane = tid & 31;
    const int gy = lane >> 2;
    const int gx = lane & 3;
    const int qr = warp * 16;

    {
        int r = tid >> 1, c0 = (tid & 1) * 32;
        const float* qp = &g_qk[((size_t)bh*L + q0 + r)*DH + c0];
        #pragma unroll
        for (int c4 = 0; c4 < 8; c4++) {
            float4 a = *(const float4*)&qp[c4*4];
            *(uint2*)&Qs[r*HSTR + c0 + c4*4] =
                make_uint2(f22h2(a.x, a.y), f22h2(a.z, a.w));
        }
    }

    const float fq0 = (float)g_hq[(size_t)bh*L + q0 + qr + gy];
    const float fq1 = (float)g_hq[(size_t)bh*L + q0 + qr + gy + 8];

    float O[8][4];
    #pragma unroll
    for (int nt=0;nt<8;nt++)
        #pragma unroll
        for (int c=0;c<4;c++) O[nt][c] = 0.0f;
    float m0 = -INFINITY, m1 = -INFINITY, l0 = 0.0f, l1 = 0.0f;

    const int fr = tid >> 2;
    const int fc = (tid & 3) * 16;
    const int vd0 = warp * 8;

    for (int k0 = 0; k0 < L; k0 += 64) {
        float4 kr[4];
        {
            const float* kp = &g_qk[((size_t)bh*L + k0 + fr)*DH + fc];
            #pragma unroll
            for (int c4=0;c4<4;c4++) kr[c4] = *(const float4*)&kp[c4*4];
        }
        float4 va0, va1, vb0, vb1;
        {
            const float* vp0 = &g_v[((size_t)bh*L + k0 + 2*lane)*DH + vd0];
            va0 = *(const float4*)&vp0[0];
            va1 = *(const float4*)&vp0[4];
            vb0 = *(const float4*)&vp0[DH];
            vb1 = *(const float4*)&vp0[DH+4];
        }
        unsigned char hkb = 0;
        if (tid < 64) hkb = g_hk[(size_t)bh*L + k0 + tid];

        __syncthreads();
        #pragma unroll
        for (int c4=0;c4<4;c4++)
            *(uint2*)&Ks[fr*HSTR + fc + c4*4] =
                make_uint2(f22h2(((const float*)&kr[c4])[0], ((const float*)&kr[c4])[1]),
                           f22h2(((const float*)&kr[c4])[2], ((const float*)&kr[c4])[3]));
        {
            const float* a0p = (const float*)&va0; const float* a1p = (const float*)&va1;
            const float* b0p = (const float*)&vb0; const float* b1p = (const float*)&vb1;
            #pragma unroll
            for (int e=0;e<4;e++){
                *(uint32_t*)&Vt[(vd0+e  )*HSTR + 2*lane] = f22h2(a0p[e], b0p[e]);
                *(uint32_t*)&Vt[(vd0+e+4)*HSTR + 2*lane] = f22h2(a1p[e], b1p[e]);
            }
        }
        if (tid < 64) hkf[tid] = (float)hkb;
        __syncthreads();

        float S[8][4];
        #pragma unroll
        for (int nt=0;nt<8;nt++)
            #pragma unroll
            for (int c=0;c<4;c++) S[nt][c] = 0.0f;

        #pragma unroll
        for (int ks = 0; ks < 4; ks++) {
            uint32_t a0 = *(uint32_t*)&Qs[(qr+gy  )*HSTR + ks*16 + 2*gx];
            uint32_t a1 = *(uint32_t*)&Qs[(qr+gy+8)*HSTR + ks*16 + 2*gx];
            uint32_t a2 = *(uint32_t*)&Qs[(qr+gy  )*HSTR + ks*16 + 2*gx + 8];
            uint32_t a3 = *(uint32_t*)&Qs[(qr+gy+8)*HSTR + ks*16 + 2*gx + 8];
            #pragma unroll
            for (int nt = 0; nt < 8; nt++) {
                uint32_t b0 = *(uint32_t*)&Ks[(nt*8+gy)*HSTR + ks*16 + 2*gx];
                uint32_t b1 = *(uint32_t*)&Ks[(nt*8+gy)*HSTR + ks*16 + 2*gx + 8];
                mma_f16(S[nt], a0, a1, a2, a3, b0, b1);
            }
        }

        float mx0 = -INFINITY, mx1 = -INFINITY;
        #pragma unroll
        for (int nt = 0; nt < 8; nt++) {
            float fk0 = hkf[nt*8 + 2*gx];
            float fk1 = hkf[nt*8 + 2*gx + 1];
            S[nt][0] = fmaf(S[nt][0], 0.125f, -1e4f*fabsf(fq0 - fk0));
            S[nt][1] = fmaf(S[nt][1], 0.125f, -1e4f*fabsf(fq0 - fk1));
            S[nt][2] = fmaf(S[nt][2], 0.125f, -1e4f*fabsf(fq1 - fk0));
            S[nt][3] = fmaf(S[nt][3], 0.125f, -1e4f*fabsf(fq1 - fk1));
            mx0 = fmaxf(mx0, fmaxf(S[nt][0], S[nt][1]));
            mx1 = fmaxf(mx1, fmaxf(S[nt][2], S[nt][3]));
        }
        #pragma unroll
        for (int o = 1; o <= 2; o <<= 1) {
            mx0 = fmaxf(mx0, __shfl_xor_sync(0xffffffffu, mx0, o));
            mx1 = fmaxf(mx1, __shfl_xor_sync(0xffffffffu, mx1, o));
        }
        float mn0 = fmaxf(m0, mx0), mn1 = fmaxf(m1, mx1);
        float cr0 = __expf(m0 - mn0), cr1 = __expf(m1 - mn1);
        m0 = mn0; m1 = mn1;

        float s0 = 0.0f, s1 = 0.0f;
        #pragma unroll
        for (int nt = 0; nt < 8; nt++) {
            float p0 = __expf(S[nt][0] - mn0);
            float p1 = __expf(S[nt][1] - mn0);
            float p2 = __expf(S[nt][2] - mn1);
            float p3 = __expf(S[nt][3] - mn1);
            s0 += p0 + p1; s1 += p2 + p3;
            *(uint32_t*)&Ps[(qr+gy  )*HSTR + nt*8 + 2*gx] = f22h2(p0, p1);
            *(uint32_t*)&Ps[(qr+gy+8)*HSTR + nt*8 + 2*gx] = f22h2(p2, p3);
        }
        #pragma unroll
        for (int o = 1; o <= 2; o <<= 1) {
            s0 += __shfl_xor_sync(0xffffffffu, s0, o);
            s1 += __shfl_xor_sync(0xffffffffu, s1, o);
        }
        l0 = l0*cr0 + s0;
        l1 = l1*cr1 + s1;

        #pragma unroll
        for (int nt = 0; nt < 8; nt++) {
            O[nt][0] *= cr0; O[nt][1] *= cr0;
            O[nt][2] *= cr1; O[nt][3] *= cr1;
        }
        __syncwarp();

        #pragma unroll
        for (int ks = 0; ks < 4; ks++) {
            uint32_t a0 = *(uint32_t*)&Ps[(qr+gy  )*HSTR + ks*16 + 2*gx];
            uint32_t a1 = *(uint32_t*)&Ps[(qr+gy+8)*HSTR + ks*16 + 2*gx];
            uint32_t a2 = *(uint32_t*)&Ps[(qr+gy  )*HSTR + ks*16 + 2*gx + 8];
            uint32_t a3 = *(uint32_t*)&Ps[(qr+gy+8)*HSTR + ks*16 + 2*gx + 8];
            #pragma unroll
            for (int nt = 0; nt < 8; nt++) {
                uint32_t b0 = *(uint32_t*)&Vt[(nt*8+gy)*HSTR + ks*16 + 2*gx];
                uint32_t b1 = *(uint32_t*)&Vt[(nt*8+gy)*HSTR + ks*16 + 2*gx + 8];
                mma_f16(O[nt], a0, a1, a2, a3, b0, b1);
            }
        }
    }

    const int bb = bh >> 4, hh = bh & 15;
    const float inv0 = 1.0f / l0, inv1 = 1.0f / l1;
    const int l_0 = q0 + qr + gy, l_1 = l_0 + 8;
    float* o0 = &out[((size_t)bb*L + l_0)*DIMM + hh*DH];
    float* o1 = &out[((size_t)bb*L + l_1)*DIMM + hh*DH];
    #pragma unroll
    for (int nt = 0; nt < 8; nt++) {
        *(float2*)&o0[nt*8 + 2*gx] = make_float2(O[nt][0]*inv0, O[nt][1]*inv0);
        *(float2*)&o1[nt*8 + 2*gx] = make_float2(O[nt][2]*inv1, O[nt][3]*inv1);
    }
}

// ---------------- launch ----------------
extern "C" void kernel_launch(void* const* d_in, const int* in_sizes, int n_in,
                              void* d_out, int out_size) {
    const float* X  = (const float*)d_in[0];
    const float* Wq = (const float*)d_in[1];
    const float* bq = (const float*)d_in[2];
    const float* Wv = (const float*)d_in[3];
    const float* bv = (const float*)d_in[4];
    const float* ha = (const float*)d_in[5];
    float* out = (float*)d_out;

    cudaFuncSetAttribute(proj_h_kernel<true>,  cudaFuncAttributeMaxDynamicSharedMemorySize, PROJ_H_SPLIT_BYTES);
    cudaFuncSetAttribute(proj_h_kernel<false>, cudaFuncAttributeMaxDynamicSharedMemorySize, PROJ_H_PLAIN_BYTES);
    cudaFuncSetAttribute(attn_kernel, cudaFuncAttributeMaxDynamicSharedMemorySize, ASM_BYTES);

    init_maxn_kernel<<<1, 32>>>();

    dim3 pg(DIMM/64, TOK/128);
    proj_h_kernel<true ><<<pg, 256, PROJ_H_SPLIT_BYTES>>>(X, Wq, bq, ha);  // qk + hash1 fused
    proj_h_kernel<false><<<pg, 256, PROJ_H_PLAIN_BYTES>>>(X, Wv, bv, ha);  // v

    hash2_kernel<<<(BH*L)/256, 256>>>(ha);

    dim3 ag(L/128, BH);
    attn_kernel<<<ag, 256, ASM_BYTES>>>(out);
}

// round 8
// speedup vs baseline: 1.1672x; 1.0189x over previous
#include <cuda_runtime.h>
#include <cuda_fp16.h>
#include <math.h>
#include <stdint.h>

#define B 2
#define L 2048
#define DIMM 1024
#define H 16
#define DH 64
#define BH (B*H)      // 32
#define TOK (B*L)     // 4096

// ---------------- scratch ----------------
__device__ float g_qk[BH*L*DH];
__device__ float g_v [BH*L*DH];
__device__ float g_dot[BH*L];
__device__ float g_norm2[BH*L];
__device__ unsigned int g_maxn2[BH];
__device__ unsigned char g_hq[BH*L];
__device__ unsigned char g_hk[BH*L];
// fp16 pre-split operands
__device__ __half g_XH [TOK*DIMM];
__device__ __half g_XL [TOK*DIMM];
__device__ __half g_WqH[DIMM*DIMM];
__device__ __half g_WqL[DIMM*DIMM];
__device__ __half g_WvH[DIMM*DIMM];

__device__ __forceinline__ uint32_t f22h2(float a, float b){
    __half2 h = __floats2half2_rn(a, b);
    return *(uint32_t*)&h;
}

__device__ __forceinline__ void mma_f16(float c[4],
    uint32_t a0, uint32_t a1, uint32_t a2, uint32_t a3,
    uint32_t b0, uint32_t b1)
{
    asm("mma.sync.aligned.m16n8k16.row.col.f32.f16.f16.f32 "
        "{%0,%1,%2,%3}, {%4,%5,%6,%7}, {%8,%9}, {%0,%1,%2,%3};"
        : "+f"(c[0]), "+f"(c[1]), "+f"(c[2]), "+f"(c[3])
        : "r"(a0), "r"(a1), "r"(a2), "r"(a3), "r"(b0), "r"(b1));
}

// ============ split conversion: fp32 -> fp16 hi (+ scaled lo residual) ============
__global__ __launch_bounds__(256)
void cvt_kernel(const float* __restrict__ src, __half* __restrict__ dh,
                __half* __restrict__ dl, int n4, int makeLo)
{
    int i = blockIdx.x*blockDim.x + threadIdx.x;
    if (i >= n4) return;
    float4 v = ((const float4*)src)[i];
    __half2 h0 = __floats2half2_rn(v.x, v.y);
    __half2 h1 = __floats2half2_rn(v.z, v.w);
    ((__half2*)dh)[2*i]   = h0;
    ((__half2*)dh)[2*i+1] = h1;
    if (makeLo) {
        __half2 l0 = __floats2half2_rn((v.x - __low2float(h0))*2048.0f,
                                       (v.y - __high2float(h0))*2048.0f);
        __half2 l1 = __floats2half2_rn((v.z - __low2float(h1))*2048.0f,
                                       (v.w - __high2float(h1))*2048.0f);
        ((__half2*)dl)[2*i]   = l0;
        ((__half2*)dl)[2*i+1] = l1;
    }
}

// ============ fp16 tensor-core projection, both mats in one launch ============
// blockIdx.z==0: qk projection, 3-term split-fp16 + fused hash stage-1.
// blockIdx.z==1: v projection, single fp16 pass.
#define HPSTR 72
#define PH_XH 0
#define PH_WH (128*HPSTR)            // 9216
#define PH_XL (PH_WH + 64*HPSTR)     // 13824
#define PH_WL (PH_XL + 128*HPSTR)    // 23040
#define PROJ_SM_BYTES ((PH_WL + 64*HPSTR)*2)   // 55296

__global__ __launch_bounds__(256, 2)
void proj_h_kernel(const float* __restrict__ bq,
                   const float* __restrict__ bv,
                   const float* __restrict__ ha)
{
    extern __shared__ __half hsm[];
    __half* XH = hsm + PH_XH;
    __half* WH = hsm + PH_WH;
    __half* XL = hsm + PH_XL;
    __half* WL = hsm + PH_WL;

    const bool SPLIT = (blockIdx.z == 0);
    float* out = SPLIT ? g_qk : g_v;
    const __half* WHg = SPLIT ? g_WqH : g_WvH;
    const float* bias = SPLIT ? bq : bv;

    const int m0 = blockIdx.y * 128;
    const int n0 = blockIdx.x * 64;
    const int tid = threadIdx.x;
    const int warp = tid >> 5;
    const int lane = tid & 31;
    const int gy = lane >> 2;
    const int gx = lane & 3;
    const int qr = warp * 16;

    const int fxr = tid >> 1;          // 0..127
    const int fxc = (tid & 1) * 16;    // halves
    const int fwr = tid >> 2;          // 0..63
    const int fwc = (tid & 3) * 8;     // halves

    float acc1[8][4];
    float acc2[8][4];
    #pragma unroll
    for (int nt=0;nt<8;nt++)
        #pragma unroll
        for (int c=0;c<4;c++){ acc1[nt][c] = 0.0f; acc2[nt][c] = 0.0f; }

    const __half* xhp = &g_XH[(size_t)(m0+fxr)*DIMM + fxc];
    const __half* xlp = &g_XL[(size_t)(m0+fxr)*DIMM + fxc];
    const __half* whp = &WHg  [(size_t)(n0+fwr)*DIMM + fwc];
    const __half* wlp = &g_WqL[(size_t)(n0+fwr)*DIMM + fwc];

    for (int kk = 0; kk < DIMM; kk += 32) {
        // prefetch fp16 chunks to regs
        uint4 xh0 = *(const uint4*)&xhp[kk];
        uint4 xh1 = *(const uint4*)&xhp[kk+8];
        uint4 wh  = *(const uint4*)&whp[kk];
        uint4 xl0, xl1, wl;
        if (SPLIT) {
            xl0 = *(const uint4*)&xlp[kk];
            xl1 = *(const uint4*)&xlp[kk+8];
            wl  = *(const uint4*)&wlp[kk];
        }

        __syncthreads();
        *(uint4*)&XH[fxr*HPSTR + fxc]     = xh0;
        *(uint4*)&XH[fxr*HPSTR + fxc + 8] = xh1;
        *(uint4*)&WH[fwr*HPSTR + fwc]     = wh;
        if (SPLIT) {
            *(uint4*)&XL[fxr*HPSTR + fxc]     = xl0;
            *(uint4*)&XL[fxr*HPSTR + fxc + 8] = xl1;
            *(uint4*)&WL[fwr*HPSTR + fwc]     = wl;
        }
        __syncthreads();

        #pragma unroll
        for (int ks = 0; ks < 2; ks++) {
            uint32_t ah0 = *(uint32_t*)&XH[(qr+gy  )*HPSTR + ks*16 + 2*gx];
            uint32_t ah1 = *(uint32_t*)&XH[(qr+gy+8)*HPSTR + ks*16 + 2*gx];
            uint32_t ah2 = *(uint32_t*)&XH[(qr+gy  )*HPSTR + ks*16 + 2*gx + 8];
            uint32_t ah3 = *(uint32_t*)&XH[(qr+gy+8)*HPSTR + ks*16 + 2*gx + 8];
            uint32_t al0=0, al1=0, al2=0, al3=0;
            if (SPLIT) {
                al0 = *(uint32_t*)&XL[(qr+gy  )*HPSTR + ks*16 + 2*gx];
                al1 = *(uint32_t*)&XL[(qr+gy+8)*HPSTR + ks*16 + 2*gx];
                al2 = *(uint32_t*)&XL[(qr+gy  )*HPSTR + ks*16 + 2*gx + 8];
                al3 = *(uint32_t*)&XL[(qr+gy+8)*HPSTR + ks*16 + 2*gx + 8];
            }
            #pragma unroll
            for (int nt = 0; nt < 8; nt++) {
                uint32_t bh0 = *(uint32_t*)&WH[(nt*8+gy)*HPSTR + ks*16 + 2*gx];
                uint32_t bh1 = *(uint32_t*)&WH[(nt*8+gy)*HPSTR + ks*16 + 2*gx + 8];
                mma_f16(acc1[nt], ah0, ah1, ah2, ah3, bh0, bh1);
                if (SPLIT) {
                    uint32_t bl0 = *(uint32_t*)&WL[(nt*8+gy)*HPSTR + ks*16 + 2*gx];
                    uint32_t bl1 = *(uint32_t*)&WL[(nt*8+gy)*HPSTR + ks*16 + 2*gx + 8];
                    mma_f16(acc2[nt], ah0, ah1, ah2, ah3, bl0, bl1);
                    mma_f16(acc2[nt], al0, al1, al2, al3, bh0, bh1);
                }
            }
        }
    }

    const int hh = blockIdx.x;
    const int m_0 = m0 + qr + gy;
    const int m_1 = m_0 + 8;
    const int b0_ = m_0 >> 11, l0_ = m_0 & (L-1);
    const int b1_ = m_1 >> 11, l1_ = m_1 & (L-1);
    float* o0 = &out[(((size_t)(b0_*H + hh)*L + l0_)*DH)];
    float* o1 = &out[(((size_t)(b1_*H + hh)*L + l1_)*DH)];

    const float inv2048 = 1.0f/2048.0f;
    float dot0 = 0.f, n20 = 0.f, dot1 = 0.f, n21 = 0.f;
    #pragma unroll
    for (int nt = 0; nt < 8; nt++) {
        float bs0 = bias[hh*64 + nt*8 + 2*gx];
        float bs1 = bias[hh*64 + nt*8 + 2*gx + 1];
        float v00, v01, v10, v11;
        if (SPLIT) {
            v00 = fmaf(acc2[nt][0], inv2048, acc1[nt][0]) + bs0;
            v01 = fmaf(acc2[nt][1], inv2048, acc1[nt][1]) + bs1;
            v10 = fmaf(acc2[nt][2], inv2048, acc1[nt][2]) + bs0;
            v11 = fmaf(acc2[nt][3], inv2048, acc1[nt][3]) + bs1;
        } else {
            v00 = acc1[nt][0] + bs0; v01 = acc1[nt][1] + bs1;
            v10 = acc1[nt][2] + bs0; v11 = acc1[nt][3] + bs1;
        }
        *(float2*)&o0[nt*8 + 2*gx] = make_float2(v00, v01);
        *(float2*)&o1[nt*8 + 2*gx] = make_float2(v10, v11);
        if (SPLIT) {
            float a0 = ha[nt*8 + 2*gx], a1 = ha[nt*8 + 2*gx + 1];
            dot0 = fmaf(v00, a0, fmaf(v01, a1, dot0));
            dot1 = fmaf(v10, a0, fmaf(v11, a1, dot1));
            n20  = fmaf(v00, v00, fmaf(v01, v01, n20));
            n21  = fmaf(v10, v10, fmaf(v11, v11, n21));
        }
    }
    if (SPLIT) {
        #pragma unroll
        for (int o = 1; o <= 2; o <<= 1) {
            dot0 += __shfl_xor_sync(0xffffffffu, dot0, o);
            dot1 += __shfl_xor_sync(0xffffffffu, dot1, o);
            n20  += __shfl_xor_sync(0xffffffffu, n20, o);
            n21  += __shfl_xor_sync(0xffffffffu, n21, o);
        }
        if (gx == 0) {
            size_t gw0 = (size_t)(b0_*H + hh)*L + l0_;
            size_t gw1 = (size_t)(b1_*H + hh)*L + l1_;
            g_dot[gw0] = dot0; g_norm2[gw0] = n20;
            g_dot[gw1] = dot1; g_norm2[gw1] = n21;
            atomicMax(&g_maxn2[b0_*H + hh], __float_as_uint(n20));
            atomicMax(&g_maxn2[b1_*H + hh], __float_as_uint(n21));
        }
    }
}

// ---------------- hash ----------------
__global__ void init_maxn_kernel() {
    if (threadIdx.x < BH) g_maxn2[threadIdx.x] = 0u;
}

__global__ void hash2_kernel(const float* __restrict__ ha) {
    int t = blockIdx.x * blockDim.x + threadIdx.x;
    if (t >= BH*L) return;
    float dot = g_dot[t], n2 = g_norm2[t];
    float maxn = sqrtf(__uint_as_float(g_maxn2[t >> 11]));
    float s = 0.75f / fmaxf(maxn, 1e-12f);
    float nk2 = s*s*n2;
    float hkval = s*dot + (0.5f - nk2)*ha[DH] + (0.5f - nk2*nk2)*ha[DH+1];
    g_hq[t] = (dot   >= 0.0f) ? 1 : 0;
    g_hk[t] = (hkval >= 0.0f) ? 1 : 0;
}

// ============ fp16 tensor-core flash attention (unchanged from R5) ============
#define HSTR 72

#define QS_OFF 0
#define KS_OFF (128*HSTR)
#define VT_OFF (KS_OFF + 64*HSTR)
#define PS_OFF (VT_OFF + 64*HSTR)
#define HK_OFF (PS_OFF + 128*HSTR)
#define ASM_HALVES (HK_OFF + 128)
#define ASM_BYTES (ASM_HALVES*2)

__global__ __launch_bounds__(256, 2)
void attn_kernel(float* __restrict__ out) {
    extern __shared__ __half smh[];
    __half* Qs = smh + QS_OFF;
    __half* Ks = smh + KS_OFF;
    __half* Vt = smh + VT_OFF;
    __half* Ps = smh + PS_OFF;
    float* hkf = (float*)(smh + HK_OFF);

    const int bh = blockIdx.y;
    const int q0 = blockIdx.x * 128;
    const int tid = threadIdx.x;
    const int warp = tid >> 5;
    const int lane = tid & 31;
    const int gy = lane >> 2;
    const int gx = lane & 3;
    const int qr = warp * 16;

    {
        int r = tid >> 1, c0 = (tid & 1) * 32;
        const float* qp = &g_qk[((size_t)bh*L + q0 + r)*DH + c0];
        #pragma unroll
        for (int c4 = 0; c4 < 8; c4++) {
            float4 a = *(const float4*)&qp[c4*4];
            *(uint2*)&Qs[r*HSTR + c0 + c4*4] =
                make_uint2(f22h2(a.x, a.y), f22h2(a.z, a.w));
        }
    }

    const float fq0 = (float)g_hq[(size_t)bh*L + q0 + qr + gy];
    const float fq1 = (float)g_hq[(size_t)bh*L + q0 + qr + gy + 8];

    float O[8][4];
    #pragma unroll
    for (int nt=0;nt<8;nt++)
        #pragma unroll
        for (int c=0;c<4;c++) O[nt][c] = 0.0f;
    float m0 = -INFINITY, m1 = -INFINITY, l0 = 0.0f, l1 = 0.0f;

    const int fr = tid >> 2;
    const int fc = (tid & 3) * 16;
    const int vd0 = warp * 8;

    for (int k0 = 0; k0 < L; k0 += 64) {
        float4 kr[4];
        {
            const float* kp = &g_qk[((size_t)bh*L + k0 + fr)*DH + fc];
            #pragma unroll
            for (int c4=0;c4<4;c4++) kr[c4] = *(const float4*)&kp[c4*4];
        }
        float4 va0, va1, vb0, vb1;
        {
            const float* vp0 = &g_v[((size_t)bh*L + k0 + 2*lane)*DH + vd0];
            va0 = *(const float4*)&vp0[0];
            va1 = *(const float4*)&vp0[4];
            vb0 = *(const float4*)&vp0[DH];
            vb1 = *(const float4*)&vp0[DH+4];
        }
        unsigned char hkb = 0;
        if (tid < 64) hkb = g_hk[(size_t)bh*L + k0 + tid];

        __syncthreads();
        #pragma unroll
        for (int c4=0;c4<4;c4++)
            *(uint2*)&Ks[fr*HSTR + fc + c4*4] =
                make_uint2(f22h2(((const float*)&kr[c4])[0], ((const float*)&kr[c4])[1]),
                           f22h2(((const float*)&kr[c4])[2], ((const float*)&kr[c4])[3]));
        {
            const float* a0p = (const float*)&va0; const float* a1p = (const float*)&va1;
            const float* b0p = (const float*)&vb0; const float* b1p = (const float*)&vb1;
            #pragma unroll
            for (int e=0;e<4;e++){
                *(uint32_t*)&Vt[(vd0+e  )*HSTR + 2*lane] = f22h2(a0p[e], b0p[e]);
                *(uint32_t*)&Vt[(vd0+e+4)*HSTR + 2*lane] = f22h2(a1p[e], b1p[e]);
            }
        }
        if (tid < 64) hkf[tid] = (float)hkb;
        __syncthreads();

        float S[8][4];
        #pragma unroll
        for (int nt=0;nt<8;nt++)
            #pragma unroll
            for (int c=0;c<4;c++) S[nt][c] = 0.0f;

        #pragma unroll
        for (int ks = 0; ks < 4; ks++) {
            uint32_t a0 = *(uint32_t*)&Qs[(qr+gy  )*HSTR + ks*16 + 2*gx];
            uint32_t a1 = *(uint32_t*)&Qs[(qr+gy+8)*HSTR + ks*16 + 2*gx];
            uint32_t a2 = *(uint32_t*)&Qs[(qr+gy  )*HSTR + ks*16 + 2*gx + 8];
            uint32_t a3 = *(uint32_t*)&Qs[(qr+gy+8)*HSTR + ks*16 + 2*gx + 8];
            #pragma unroll
            for (int nt = 0; nt < 8; nt++) {
                uint32_t b0 = *(uint32_t*)&Ks[(nt*8+gy)*HSTR + ks*16 + 2*gx];
                uint32_t b1 = *(uint32_t*)&Ks[(nt*8+gy)*HSTR + ks*16 + 2*gx + 8];
                mma_f16(S[nt], a0, a1, a2, a3, b0, b1);
            }
        }

        float mx0 = -INFINITY, mx1 = -INFINITY;
        #pragma unroll
        for (int nt = 0; nt < 8; nt++) {
            float fk0 = hkf[nt*8 + 2*gx];
            float fk1 = hkf[nt*8 + 2*gx + 1];
            S[nt][0] = fmaf(S[nt][0], 0.125f, -1e4f*fabsf(fq0 - fk0));
            S[nt][1] = fmaf(S[nt][1], 0.125f, -1e4f*fabsf(fq0 - fk1));
            S[nt][2] = fmaf(S[nt][2], 0.125f, -1e4f*fabsf(fq1 - fk0));
            S[nt][3] = fmaf(S[nt][3], 0.125f, -1e4f*fabsf(fq1 - fk1));
            mx0 = fmaxf(mx0, fmaxf(S[nt][0], S[nt][1]));
            mx1 = fmaxf(mx1, fmaxf(S[nt][2], S[nt][3]));
        }
        #pragma unroll
        for (int o = 1; o <= 2; o <<= 1) {
            mx0 = fmaxf(mx0, __shfl_xor_sync(0xffffffffu, mx0, o));
            mx1 = fmaxf(mx1, __shfl_xor_sync(0xffffffffu, mx1, o));
        }
        float mn0 = fmaxf(m0, mx0), mn1 = fmaxf(m1, mx1);
        float cr0 = __expf(m0 - mn0), cr1 = __expf(m1 - mn1);
        m0 = mn0; m1 = mn1;

        float s0 = 0.0f, s1 = 0.0f;
        #pragma unroll
        for (int nt = 0; nt < 8; nt++) {
            float p0 = __expf(S[nt][0] - mn0);
            float p1 = __expf(S[nt][1] - mn0);
            float p2 = __expf(S[nt][2] - mn1);
            float p3 = __expf(S[nt][3] - mn1);
            s0 += p0 + p1; s1 += p2 + p3;
            *(uint32_t*)&Ps[(qr+gy  )*HSTR + nt*8 + 2*gx] = f22h2(p0, p1);
            *(uint32_t*)&Ps[(qr+gy+8)*HSTR + nt*8 + 2*gx] = f22h2(p2, p3);
        }
        #pragma unroll
        for (int o = 1; o <= 2; o <<= 1) {
            s0 += __shfl_xor_sync(0xffffffffu, s0, o);
            s1 += __shfl_xor_sync(0xffffffffu, s1, o);
        }
        l0 = l0*cr0 + s0;
        l1 = l1*cr1 + s1;

        #pragma unroll
        for (int nt = 0; nt < 8; nt++) {
            O[nt][0] *= cr0; O[nt][1] *= cr0;
            O[nt][2] *= cr1; O[nt][3] *= cr1;
        }
        __syncwarp();

        #pragma unroll
        for (int ks = 0; ks < 4; ks++) {
            uint32_t a0 = *(uint32_t*)&Ps[(qr+gy  )*HSTR + ks*16 + 2*gx];
            uint32_t a1 = *(uint32_t*)&Ps[(qr+gy+8)*HSTR + ks*16 + 2*gx];
            uint32_t a2 = *(uint32_t*)&Ps[(qr+gy  )*HSTR + ks*16 + 2*gx + 8];
            uint32_t a3 = *(uint32_t*)&Ps[(qr+gy+8)*HSTR + ks*16 + 2*gx + 8];
            #pragma unroll
            for (int nt = 0; nt < 8; nt++) {
                uint32_t b0 = *(uint32_t*)&Vt[(nt*8+gy)*HSTR + ks*16 + 2*gx];
                uint32_t b1 = *(uint32_t*)&Vt[(nt*8+gy)*HSTR + ks*16 + 2*gx + 8];
                mma_f16(O[nt], a0, a1, a2, a3, b0, b1);
            }
        }
    }

    const int bb = bh >> 4, hh = bh & 15;
    const float inv0 = 1.0f / l0, inv1 = 1.0f / l1;
    const int l_0 = q0 + qr + gy, l_1 = l_0 + 8;
    float* o0 = &out[((size_t)bb*L + l_0)*DIMM + hh*DH];
    float* o1 = &out[((size_t)bb*L + l_1)*DIMM + hh*DH];
    #pragma unroll
    for (int nt = 0; nt < 8; nt++) {
        *(float2*)&o0[nt*8 + 2*gx] = make_float2(O[nt][0]*inv0, O[nt][1]*inv0);
        *(float2*)&o1[nt*8 + 2*gx] = make_float2(O[nt][2]*inv1, O[nt][3]*inv1);
    }
}

// ---------------- launch ----------------
extern "C" void kernel_launch(void* const* d_in, const int* in_sizes, int n_in,
                              void* d_out, int out_size) {
    const float* X  = (const float*)d_in[0];
    const float* Wq = (const float*)d_in[1];
    const float* bq = (const float*)d_in[2];
    const float* Wv = (const float*)d_in[3];
    const float* bv = (const float*)d_in[4];
    const float* ha = (const float*)d_in[5];
    float* out = (float*)d_out;

    cudaFuncSetAttribute(proj_h_kernel, cudaFuncAttributeMaxDynamicSharedMemorySize, PROJ_SM_BYTES);
    cudaFuncSetAttribute(attn_kernel,   cudaFuncAttributeMaxDynamicSharedMemorySize, ASM_BYTES);

    init_maxn_kernel<<<1, 32>>>();

    // pre-split conversions
    __half *xh, *xl, *wqh, *wql, *wvh;
    cudaGetSymbolAddress((void**)&xh,  g_XH);
    cudaGetSymbolAddress((void**)&xl,  g_XL);
    cudaGetSymbolAddress((void**)&wqh, g_WqH);
    cudaGetSymbolAddress((void**)&wql, g_WqL);
    cudaGetSymbolAddress((void**)&wvh, g_WvH);
    cvt_kernel<<<(TOK*DIMM/4)/256, 256>>>(X,  xh,  xl,  TOK*DIMM/4, 1);
    cvt_kernel<<<(DIMM*DIMM/4)/256, 256>>>(Wq, wqh, wql, DIMM*DIMM/4, 1);
    cvt_kernel<<<(DIMM*DIMM/4)/256, 256>>>(Wv, wvh, wvh, DIMM*DIMM/4, 0);

    dim3 pg(DIMM/64, TOK/128, 2);
    proj_h_kernel<<<pg, 256, PROJ_SM_BYTES>>>(bq, bv, ha);

    hash2_kernel<<<(BH*L)/256, 256>>>(ha);

    dim3 ag(L/128, BH);
    attn_kernel<<<ag, 256, ASM_BYTES>>>(out);
}

// round 9
// speedup vs baseline: 1.3487x; 1.1555x over previous
#include <cuda_runtime.h>
#include <cuda_fp16.h>
#include <math.h>
#include <stdint.h>

#define B 2
#define L 2048
#define DIMM 1024
#define H 16
#define DH 64
#define BH (B*H)      // 32
#define TOK (B*L)     // 4096

// ---------------- scratch ----------------
__device__ __half g_qkh[BH*L*DH];        // (b,h,l,d) fp16
__device__ __half g_vh [BH*L*DH];        // (b,h,l,d) fp16
__device__ float g_dot[BH*L];
__device__ float g_norm2[BH*L];
__device__ unsigned int g_maxn2[BH];
__device__ unsigned char g_hq[BH*L];
__device__ unsigned char g_hk[BH*L];
// fp16 pre-split operands
__device__ __half g_XH [TOK*DIMM];
__device__ __half g_XL [TOK*DIMM];
__device__ __half g_WqH[DIMM*DIMM];
__device__ __half g_WqL[DIMM*DIMM];
__device__ __half g_WvH[DIMM*DIMM];

__device__ __forceinline__ uint32_t f22h2(float a, float b){
    __half2 h = __floats2half2_rn(a, b);
    return *(uint32_t*)&h;
}

__device__ __forceinline__ void mma_f16(float c[4],
    uint32_t a0, uint32_t a1, uint32_t a2, uint32_t a3,
    uint32_t b0, uint32_t b1)
{
    asm("mma.sync.aligned.m16n8k16.row.col.f32.f16.f16.f32 "
        "{%0,%1,%2,%3}, {%4,%5,%6,%7}, {%8,%9}, {%0,%1,%2,%3};"
        : "+f"(c[0]), "+f"(c[1]), "+f"(c[2]), "+f"(c[3])
        : "r"(a0), "r"(a1), "r"(a2), "r"(a3), "r"(b0), "r"(b1));
}

// ============ split conversion: fp32 -> fp16 hi (+ scaled lo residual) ============
__global__ __launch_bounds__(256)
void cvt_kernel(const float* __restrict__ src, __half* __restrict__ dh,
                __half* __restrict__ dl, int n4, int makeLo)
{
    int i = blockIdx.x*blockDim.x + threadIdx.x;
    if (i >= n4) return;
    float4 v = ((const float4*)src)[i];
    __half2 h0 = __floats2half2_rn(v.x, v.y);
    __half2 h1 = __floats2half2_rn(v.z, v.w);
    ((__half2*)dh)[2*i]   = h0;
    ((__half2*)dh)[2*i+1] = h1;
    if (makeLo) {
        __half2 l0 = __floats2half2_rn((v.x - __low2float(h0))*2048.0f,
                                       (v.y - __high2float(h0))*2048.0f);
        __half2 l1 = __floats2half2_rn((v.z - __low2float(h1))*2048.0f,
                                       (v.w - __high2float(h1))*2048.0f);
        ((__half2*)dl)[2*i]   = l0;
        ((__half2*)dl)[2*i+1] = l1;
    }
}

// ============ fp16 tensor-core projection, both mats in one launch ============
#define HPSTR 72
#define PH_XH 0
#define PH_WH (128*HPSTR)
#define PH_XL (PH_WH + 64*HPSTR)
#define PH_WL (PH_XL + 128*HPSTR)
#define PROJ_SM_BYTES ((PH_WL + 64*HPSTR)*2)   // 55296

__global__ __launch_bounds__(256, 2)
void proj_h_kernel(const float* __restrict__ bq,
                   const float* __restrict__ bv,
                   const float* __restrict__ ha)
{
    extern __shared__ __half hsm[];
    __half* XH = hsm + PH_XH;
    __half* WH = hsm + PH_WH;
    __half* XL = hsm + PH_XL;
    __half* WL = hsm + PH_WL;

    const bool SPLIT = (blockIdx.z == 0);
    __half* out = SPLIT ? g_qkh : g_vh;
    const __half* WHg = SPLIT ? g_WqH : g_WvH;
    const float* bias = SPLIT ? bq : bv;

    const int m0 = blockIdx.y * 128;
    const int n0 = blockIdx.x * 64;
    const int tid = threadIdx.x;
    const int warp = tid >> 5;
    const int lane = tid & 31;
    const int gy = lane >> 2;
    const int gx = lane & 3;
    const int qr = warp * 16;

    const int fxr = tid >> 1;
    const int fxc = (tid & 1) * 16;
    const int fwr = tid >> 2;
    const int fwc = (tid & 3) * 8;

    float acc1[8][4];
    float acc2[8][4];
    #pragma unroll
    for (int nt=0;nt<8;nt++)
        #pragma unroll
        for (int c=0;c<4;c++){ acc1[nt][c] = 0.0f; acc2[nt][c] = 0.0f; }

    const __half* xhp = &g_XH[(size_t)(m0+fxr)*DIMM + fxc];
    const __half* xlp = &g_XL[(size_t)(m0+fxr)*DIMM + fxc];
    const __half* whp = &WHg  [(size_t)(n0+fwr)*DIMM + fwc];
    const __half* wlp = &g_WqL[(size_t)(n0+fwr)*DIMM + fwc];

    for (int kk = 0; kk < DIMM; kk += 32) {
        uint4 xh0 = *(const uint4*)&xhp[kk];
        uint4 xh1 = *(const uint4*)&xhp[kk+8];
        uint4 wh  = *(const uint4*)&whp[kk];
        uint4 xl0, xl1, wl;
        if (SPLIT) {
            xl0 = *(const uint4*)&xlp[kk];
            xl1 = *(const uint4*)&xlp[kk+8];
            wl  = *(const uint4*)&wlp[kk];
        }

        __syncthreads();
        *(uint4*)&XH[fxr*HPSTR + fxc]     = xh0;
        *(uint4*)&XH[fxr*HPSTR + fxc + 8] = xh1;
        *(uint4*)&WH[fwr*HPSTR + fwc]     = wh;
        if (SPLIT) {
            *(uint4*)&XL[fxr*HPSTR + fxc]     = xl0;
            *(uint4*)&XL[fxr*HPSTR + fxc + 8] = xl1;
            *(uint4*)&WL[fwr*HPSTR + fwc]     = wl;
        }
        __syncthreads();

        #pragma unroll
        for (int ks = 0; ks < 2; ks++) {
            uint32_t ah0 = *(uint32_t*)&XH[(qr+gy  )*HPSTR + ks*16 + 2*gx];
            uint32_t ah1 = *(uint32_t*)&XH[(qr+gy+8)*HPSTR + ks*16 + 2*gx];
            uint32_t ah2 = *(uint32_t*)&XH[(qr+gy  )*HPSTR + ks*16 + 2*gx + 8];
            uint32_t ah3 = *(uint32_t*)&XH[(qr+gy+8)*HPSTR + ks*16 + 2*gx + 8];
            uint32_t al0=0, al1=0, al2=0, al3=0;
            if (SPLIT) {
                al0 = *(uint32_t*)&XL[(qr+gy  )*HPSTR + ks*16 + 2*gx];
                al1 = *(uint32_t*)&XL[(qr+gy+8)*HPSTR + ks*16 + 2*gx];
                al2 = *(uint32_t*)&XL[(qr+gy  )*HPSTR + ks*16 + 2*gx + 8];
                al3 = *(uint32_t*)&XL[(qr+gy+8)*HPSTR + ks*16 + 2*gx + 8];
            }
            #pragma unroll
            for (int nt = 0; nt < 8; nt++) {
                uint32_t bh0 = *(uint32_t*)&WH[(nt*8+gy)*HPSTR + ks*16 + 2*gx];
                uint32_t bh1 = *(uint32_t*)&WH[(nt*8+gy)*HPSTR + ks*16 + 2*gx + 8];
                mma_f16(acc1[nt], ah0, ah1, ah2, ah3, bh0, bh1);
                if (SPLIT) {
                    uint32_t bl0 = *(uint32_t*)&WL[(nt*8+gy)*HPSTR + ks*16 + 2*gx];
                    uint32_t bl1 = *(uint32_t*)&WL[(nt*8+gy)*HPSTR + ks*16 + 2*gx + 8];
                    mma_f16(acc2[nt], ah0, ah1, ah2, ah3, bl0, bl1);
                    mma_f16(acc2[nt], al0, al1, al2, al3, bh0, bh1);
                }
            }
        }
    }

    const int hh = blockIdx.x;
    const int m_0 = m0 + qr + gy;
    const int m_1 = m_0 + 8;
    const int b0_ = m_0 >> 11, l0_ = m_0 & (L-1);
    const int b1_ = m_1 >> 11, l1_ = m_1 & (L-1);
    __half* o0 = &out[(((size_t)(b0_*H + hh)*L + l0_)*DH)];
    __half* o1 = &out[(((size_t)(b1_*H + hh)*L + l1_)*DH)];

    const float inv2048 = 1.0f/2048.0f;
    float dot0 = 0.f, n20 = 0.f, dot1 = 0.f, n21 = 0.f;
    #pragma unroll
    for (int nt = 0; nt < 8; nt++) {
        float bs0 = bias[hh*64 + nt*8 + 2*gx];
        float bs1 = bias[hh*64 + nt*8 + 2*gx + 1];
        float v00, v01, v10, v11;
        if (SPLIT) {
            v00 = fmaf(acc2[nt][0], inv2048, acc1[nt][0]) + bs0;
            v01 = fmaf(acc2[nt][1], inv2048, acc1[nt][1]) + bs1;
            v10 = fmaf(acc2[nt][2], inv2048, acc1[nt][2]) + bs0;
            v11 = fmaf(acc2[nt][3], inv2048, acc1[nt][3]) + bs1;
        } else {
            v00 = acc1[nt][0] + bs0; v01 = acc1[nt][1] + bs1;
            v10 = acc1[nt][2] + bs0; v11 = acc1[nt][3] + bs1;
        }
        *(uint32_t*)&o0[nt*8 + 2*gx] = f22h2(v00, v01);
        *(uint32_t*)&o1[nt*8 + 2*gx] = f22h2(v10, v11);
        if (SPLIT) {
            float a0 = ha[nt*8 + 2*gx], a1 = ha[nt*8 + 2*gx + 1];
            dot0 = fmaf(v00, a0, fmaf(v01, a1, dot0));
            dot1 = fmaf(v10, a0, fmaf(v11, a1, dot1));
            n20  = fmaf(v00, v00, fmaf(v01, v01, n20));
            n21  = fmaf(v10, v10, fmaf(v11, v11, n21));
        }
    }
    if (SPLIT) {
        #pragma unroll
        for (int o = 1; o <= 2; o <<= 1) {
            dot0 += __shfl_xor_sync(0xffffffffu, dot0, o);
            dot1 += __shfl_xor_sync(0xffffffffu, dot1, o);
            n20  += __shfl_xor_sync(0xffffffffu, n20, o);
            n21  += __shfl_xor_sync(0xffffffffu, n21, o);
        }
        if (gx == 0) {
            size_t gw0 = (size_t)(b0_*H + hh)*L + l0_;
            size_t gw1 = (size_t)(b1_*H + hh)*L + l1_;
            g_dot[gw0] = dot0; g_norm2[gw0] = n20;
            g_dot[gw1] = dot1; g_norm2[gw1] = n21;
            atomicMax(&g_maxn2[b0_*H + hh], __float_as_uint(n20));
            atomicMax(&g_maxn2[b1_*H + hh], __float_as_uint(n21));
        }
    }
}

// ---------------- hash ----------------
__global__ void init_maxn_kernel() {
    if (threadIdx.x < BH) g_maxn2[threadIdx.x] = 0u;
}

__global__ void hash2_kernel(const float* __restrict__ ha) {
    int t = blockIdx.x * blockDim.x + threadIdx.x;
    if (t >= BH*L) return;
    float dot = g_dot[t], n2 = g_norm2[t];
    float maxn = sqrtf(__uint_as_float(g_maxn2[t >> 11]));
    float s = 0.75f / fmaxf(maxn, 1e-12f);
    float nk2 = s*s*n2;
    float hkval = s*dot + (0.5f - nk2)*ha[DH] + (0.5f - nk2*nk2)*ha[DH+1];
    g_hq[t] = (dot   >= 0.0f) ? 1 : 0;
    g_hk[t] = (hkval >= 0.0f) ? 1 : 0;
}

// ============ fp16 tensor-core flash attention (fp16 in gmem; cvt-free fills) ============
#define HSTR 72

#define QS_OFF 0
#define KS_OFF (128*HSTR)
#define VT_OFF (KS_OFF + 64*HSTR)
#define PS_OFF (VT_OFF + 64*HSTR)
#define HK_OFF (PS_OFF + 128*HSTR)
#define ASM_HALVES (HK_OFF + 128)
#define ASM_BYTES (ASM_HALVES*2)

__global__ __launch_bounds__(256, 2)
void attn_kernel(float* __restrict__ out) {
    extern __shared__ __half smh[];
    __half* Qs = smh + QS_OFF;
    __half* Ks = smh + KS_OFF;
    __half* Vt = smh + VT_OFF;
    __half* Ps = smh + PS_OFF;
    float* hkf = (float*)(smh + HK_OFF);

    const int bh = blockIdx.y;
    const int q0 = blockIdx.x * 128;
    const int tid = threadIdx.x;
    const int warp = tid >> 5;
    const int lane = tid & 31;
    const int gy = lane >> 2;
    const int gx = lane & 3;
    const int qr = warp * 16;

    // ---- Q fill: straight fp16 copy ----
    {
        int r = tid >> 1, c0 = (tid & 1) * 32;
        const __half* qp = &g_qkh[((size_t)bh*L + q0 + r)*DH + c0];
        #pragma unroll
        for (int c8 = 0; c8 < 4; c8++)
            *(uint4*)&Qs[r*HSTR + c0 + c8*8] = *(const uint4*)&qp[c8*8];
    }

    const float fq0 = (float)g_hq[(size_t)bh*L + q0 + qr + gy];
    const float fq1 = (float)g_hq[(size_t)bh*L + q0 + qr + gy + 8];

    float O[8][4];
    #pragma unroll
    for (int nt=0;nt<8;nt++)
        #pragma unroll
        for (int c=0;c<4;c++) O[nt][c] = 0.0f;
    float m0 = -INFINITY, m1 = -INFINITY, l0 = 0.0f, l1 = 0.0f;

    const int fr = tid >> 2;           // K fill row 0..63
    const int fc = (tid & 3) * 16;     // halves
    const int vd0 = warp * 8;          // V^T: this warp's 8 d-rows

    for (int k0 = 0; k0 < L; k0 += 64) {
        // prefetch fp16 K chunk + V rows (for PRMT transpose)
        uint4 kA, kB;
        {
            const __half* kp = &g_qkh[((size_t)bh*L + k0 + fr)*DH + fc];
            kA = ((const uint4*)kp)[0];
            kB = ((const uint4*)kp)[1];
        }
        uint4 va, vb;
        {
            const __half* vp = &g_vh[((size_t)bh*L + k0 + 2*lane)*DH + vd0];
            va = *(const uint4*)vp;
            vb = *(const uint4*)(vp + DH);
        }
        unsigned char hkb = 0;
        if (tid < 64) hkb = g_hk[(size_t)bh*L + k0 + tid];

        __syncthreads();
        *(uint4*)&Ks[fr*HSTR + fc]     = kA;
        *(uint4*)&Ks[fr*HSTR + fc + 8] = kB;
        {
            const uint32_t* aw = (const uint32_t*)&va;
            const uint32_t* bw = (const uint32_t*)&vb;
            #pragma unroll
            for (int j=0;j<4;j++){
                uint32_t lo = __byte_perm(aw[j], bw[j], 0x5410);
                uint32_t hi = __byte_perm(aw[j], bw[j], 0x7632);
                *(uint32_t*)&Vt[(vd0+2*j  )*HSTR + 2*lane] = lo;
                *(uint32_t*)&Vt[(vd0+2*j+1)*HSTR + 2*lane] = hi;
            }
        }
        if (tid < 64) hkf[tid] = (float)hkb;
        __syncthreads();

        // ---- S = Q @ K^T ----
        float S[8][4];
        #pragma unroll
        for (int nt=0;nt<8;nt++)
            #pragma unroll
            for (int c=0;c<4;c++) S[nt][c] = 0.0f;

        #pragma unroll
        for (int ks = 0; ks < 4; ks++) {
            uint32_t a0 = *(uint32_t*)&Qs[(qr+gy  )*HSTR + ks*16 + 2*gx];
            uint32_t a1 = *(uint32_t*)&Qs[(qr+gy+8)*HSTR + ks*16 + 2*gx];
            uint32_t a2 = *(uint32_t*)&Qs[(qr+gy  )*HSTR + ks*16 + 2*gx + 8];
            uint32_t a3 = *(uint32_t*)&Qs[(qr+gy+8)*HSTR + ks*16 + 2*gx + 8];
            #pragma unroll
            for (int nt = 0; nt < 8; nt++) {
                uint32_t b0 = *(uint32_t*)&Ks[(nt*8+gy)*HSTR + ks*16 + 2*gx];
                uint32_t b1 = *(uint32_t*)&Ks[(nt*8+gy)*HSTR + ks*16 + 2*gx + 8];
                mma_f16(S[nt], a0, a1, a2, a3, b0, b1);
            }
        }

        // ---- mask + scale; row max ----
        float mx0 = -INFINITY, mx1 = -INFINITY;
        #pragma unroll
        for (int nt = 0; nt < 8; nt++) {
            float fk0 = hkf[nt*8 + 2*gx];
            float fk1 = hkf[nt*8 + 2*gx + 1];
            S[nt][0] = fmaf(S[nt][0], 0.125f, -1e4f*fabsf(fq0 - fk0));
            S[nt][1] = fmaf(S[nt][1], 0.125f, -1e4f*fabsf(fq0 - fk1));
            S[nt][2] = fmaf(S[nt][2], 0.125f, -1e4f*fabsf(fq1 - fk0));
            S[nt][3] = fmaf(S[nt][3], 0.125f, -1e4f*fabsf(fq1 - fk1));
            mx0 = fmaxf(mx0, fmaxf(S[nt][0], S[nt][1]));
            mx1 = fmaxf(mx1, fmaxf(S[nt][2], S[nt][3]));
        }
        #pragma unroll
        for (int o = 1; o <= 2; o <<= 1) {
            mx0 = fmaxf(mx0, __shfl_xor_sync(0xffffffffu, mx0, o));
            mx1 = fmaxf(mx1, __shfl_xor_sync(0xffffffffu, mx1, o));
        }
        float mn0 = fmaxf(m0, mx0), mn1 = fmaxf(m1, mx1);
        float cr0 = __expf(m0 - mn0), cr1 = __expf(m1 - mn1);
        m0 = mn0; m1 = mn1;

        float s0 = 0.0f, s1 = 0.0f;
        #pragma unroll
        for (int nt = 0; nt < 8; nt++) {
            float p0 = __expf(S[nt][0] - mn0);
            float p1 = __expf(S[nt][1] - mn0);
            float p2 = __expf(S[nt][2] - mn1);
            float p3 = __expf(S[nt][3] - mn1);
            s0 += p0 + p1; s1 += p2 + p3;
            *(uint32_t*)&Ps[(qr+gy  )*HSTR + nt*8 + 2*gx] = f22h2(p0, p1);
            *(uint32_t*)&Ps[(qr+gy+8)*HSTR + nt*8 + 2*gx] = f22h2(p2, p3);
        }
        #pragma unroll
        for (int o = 1; o <= 2; o <<= 1) {
            s0 += __shfl_xor_sync(0xffffffffu, s0, o);
            s1 += __shfl_xor_sync(0xffffffffu, s1, o);
        }
        l0 = l0*cr0 + s0;
        l1 = l1*cr1 + s1;

        #pragma unroll
        for (int nt = 0; nt < 8; nt++) {
            O[nt][0] *= cr0; O[nt][1] *= cr0;
            O[nt][2] *= cr1; O[nt][3] *= cr1;
        }
        __syncwarp();

        // ---- O += P @ V ----
        #pragma unroll
        for (int ks = 0; ks < 4; ks++) {
            uint32_t a0 = *(uint32_t*)&Ps[(qr+gy  )*HSTR + ks*16 + 2*gx];
            uint32_t a1 = *(uint32_t*)&Ps[(qr+gy+8)*HSTR + ks*16 + 2*gx];
            uint32_t a2 = *(uint32_t*)&Ps[(qr+gy  )*HSTR + ks*16 + 2*gx + 8];
            uint32_t a3 = *(uint32_t*)&Ps[(qr+gy+8)*HSTR + ks*16 + 2*gx + 8];
            #pragma unroll
            for (int nt = 0; nt < 8; nt++) {
                uint32_t b0 = *(uint32_t*)&Vt[(nt*8+gy)*HSTR + ks*16 + 2*gx];
                uint32_t b1 = *(uint32_t*)&Vt[(nt*8+gy)*HSTR + ks*16 + 2*gx + 8];
                mma_f16(O[nt], a0, a1, a2, a3, b0, b1);
            }
        }
    }

    const int bb = bh >> 4, hh = bh & 15;
    const float inv0 = 1.0f / l0, inv1 = 1.0f / l1;
    const int l_0 = q0 + qr + gy, l_1 = l_0 + 8;
    float* o0 = &out[((size_t)bb*L + l_0)*DIMM + hh*DH];
    float* o1 = &out[((size_t)bb*L + l_1)*DIMM + hh*DH];
    #pragma unroll
    for (int nt = 0; nt < 8; nt++) {
        *(float2*)&o0[nt*8 + 2*gx] = make_float2(O[nt][0]*inv0, O[nt][1]*inv0);
        *(float2*)&o1[nt*8 + 2*gx] = make_float2(O[nt][2]*inv1, O[nt][3]*inv1);
    }
}

// ---------------- launch ----------------
extern "C" void kernel_launch(void* const* d_in, const int* in_sizes, int n_in,
                              void* d_out, int out_size) {
    const float* X  = (const float*)d_in[0];
    const float* Wq = (const float*)d_in[1];
    const float* bq = (const float*)d_in[2];
    const float* Wv = (const float*)d_in[3];
    const float* bv = (const float*)d_in[4];
    const float* ha = (const float*)d_in[5];
    float* out = (float*)d_out;

    cudaFuncSetAttribute(proj_h_kernel, cudaFuncAttributeMaxDynamicSharedMemorySize, PROJ_SM_BYTES);
    cudaFuncSetAttribute(attn_kernel,   cudaFuncAttributeMaxDynamicSharedMemorySize, ASM_BYTES);

    init_maxn_kernel<<<1, 32>>>();

    __half *xh, *xl, *wqh, *wql, *wvh;
    cudaGetSymbolAddress((void**)&xh,  g_XH);
    cudaGetSymbolAddress((void**)&xl,  g_XL);
    cudaGetSymbolAddress((void**)&wqh, g_WqH);
    cudaGetSymbolAddress((void**)&wql, g_WqL);
    cudaGetSymbolAddress((void**)&wvh, g_WvH);
    cvt_kernel<<<(TOK*DIMM/4)/256, 256>>>(X,  xh,  xl,  TOK*DIMM/4, 1);
    cvt_kernel<<<(DIMM*DIMM/4)/256, 256>>>(Wq, wqh, wql, DIMM*DIMM/4, 1);
    cvt_kernel<<<(DIMM*DIMM/4)/256, 256>>>(Wv, wvh, wvh, DIMM*DIMM/4, 0);

    dim3 pg(DIMM/64, TOK/128, 2);
    proj_h_kernel<<<pg, 256, PROJ_SM_BYTES>>>(bq, bv, ha);

    hash2_kernel<<<(BH*L)/256, 256>>>(ha);

    dim3 ag(L/128, BH);
    attn_kernel<<<ag, 256, ASM_BYTES>>>(out);
}

// round 10
// speedup vs baseline: 1.4222x; 1.0545x over previous
#include <cuda_runtime.h>
#include <cuda_fp16.h>
#include <math.h>
#include <stdint.h>

#define B 2
#define L 2048
#define DIMM 1024
#define H 16
#define DH 64
#define BH (B*H)      // 32
#define TOK (B*L)     // 4096

// ---------------- scratch ----------------
__device__ __half g_qkh[BH*L*DH];        // (b,h,l,d) fp16
__device__ __half g_vh [BH*L*DH];        // (b,h,l,d) fp16
__device__ float g_dot[BH*L];
__device__ float g_norm2[BH*L];
__device__ unsigned int g_maxn2[BH];
__device__ unsigned char g_hq[BH*L];
__device__ unsigned char g_hk[BH*L];
// fp16 pre-split operands
__device__ __half g_XH [TOK*DIMM];
__device__ __half g_XL [TOK*DIMM];
__device__ __half g_WqH[DIMM*DIMM];
__device__ __half g_WqL[DIMM*DIMM];
__device__ __half g_WvH[DIMM*DIMM];

__device__ __forceinline__ uint32_t f22h2(float a, float b){
    __half2 h = __floats2half2_rn(a, b);
    return *(uint32_t*)&h;
}
__device__ __forceinline__ float ex2f(float x){
    float r; asm("ex2.approx.f32 %0, %1;" : "=f"(r) : "f"(x)); return r;
}

__device__ __forceinline__ void mma_f16(float c[4],
    uint32_t a0, uint32_t a1, uint32_t a2, uint32_t a3,
    uint32_t b0, uint32_t b1)
{
    asm("mma.sync.aligned.m16n8k16.row.col.f32.f16.f16.f32 "
        "{%0,%1,%2,%3}, {%4,%5,%6,%7}, {%8,%9}, {%0,%1,%2,%3};"
        : "+f"(c[0]), "+f"(c[1]), "+f"(c[2]), "+f"(c[3])
        : "r"(a0), "r"(a1), "r"(a2), "r"(a3), "r"(b0), "r"(b1));
}

// ============ split conversion: fp32 -> fp16 hi (+ scaled lo residual) ============
__global__ __launch_bounds__(256)
void cvt_kernel(const float* __restrict__ src, __half* __restrict__ dh,
                __half* __restrict__ dl, int n4, int makeLo)
{
    int i = blockIdx.x*blockDim.x + threadIdx.x;
    if (blockIdx.x == 0 && threadIdx.x < BH) g_maxn2[threadIdx.x] = 0u;  // fused init
    if (i >= n4) return;
    float4 v = ((const float4*)src)[i];
    __half2 h0 = __floats2half2_rn(v.x, v.y);
    __half2 h1 = __floats2half2_rn(v.z, v.w);
    ((__half2*)dh)[2*i]   = h0;
    ((__half2*)dh)[2*i+1] = h1;
    if (makeLo) {
        __half2 l0 = __floats2half2_rn((v.x - __low2float(h0))*2048.0f,
                                       (v.y - __high2float(h0))*2048.0f);
        __half2 l1 = __floats2half2_rn((v.z - __low2float(h1))*2048.0f,
                                       (v.w - __high2float(h1))*2048.0f);
        ((__half2*)dl)[2*i]   = l0;
        ((__half2*)dl)[2*i+1] = l1;
    }
}

// ============ fp16 tensor-core projection, both mats in one launch ============
#define HPSTR 72
#define PH_XH 0
#define PH_WH (128*HPSTR)
#define PH_XL (PH_WH + 64*HPSTR)
#define PH_WL (PH_XL + 128*HPSTR)
#define PROJ_SM_BYTES ((PH_WL + 64*HPSTR)*2)   // 55296

__global__ __launch_bounds__(256, 2)
void proj_h_kernel(const float* __restrict__ bq,
                   const float* __restrict__ bv,
                   const float* __restrict__ ha)
{
    extern __shared__ __half hsm[];
    __half* XH = hsm + PH_XH;
    __half* WH = hsm + PH_WH;
    __half* XL = hsm + PH_XL;
    __half* WL = hsm + PH_WL;

    const bool SPLIT = (blockIdx.z == 0);
    __half* out = SPLIT ? g_qkh : g_vh;
    const __half* WHg = SPLIT ? g_WqH : g_WvH;
    const float* bias = SPLIT ? bq : bv;

    const int m0 = blockIdx.y * 128;
    const int n0 = blockIdx.x * 64;
    const int tid = threadIdx.x;
    const int warp = tid >> 5;
    const int lane = tid & 31;
    const int gy = lane >> 2;
    const int gx = lane & 3;
    const int qr = warp * 16;

    const int fxr = tid >> 1;
    const int fxc = (tid & 1) * 16;
    const int fwr = tid >> 2;
    const int fwc = (tid & 3) * 8;

    float acc1[8][4];
    float acc2[8][4];
    #pragma unroll
    for (int nt=0;nt<8;nt++)
        #pragma unroll
        for (int c=0;c<4;c++){ acc1[nt][c] = 0.0f; acc2[nt][c] = 0.0f; }

    const __half* xhp = &g_XH[(size_t)(m0+fxr)*DIMM + fxc];
    const __half* xlp = &g_XL[(size_t)(m0+fxr)*DIMM + fxc];
    const __half* whp = &WHg  [(size_t)(n0+fwr)*DIMM + fwc];
    const __half* wlp = &g_WqL[(size_t)(n0+fwr)*DIMM + fwc];

    for (int kk = 0; kk < DIMM; kk += 32) {
        uint4 xh0 = *(const uint4*)&xhp[kk];
        uint4 xh1 = *(const uint4*)&xhp[kk+8];
        uint4 wh  = *(const uint4*)&whp[kk];
        uint4 xl0, xl1, wl;
        if (SPLIT) {
            xl0 = *(const uint4*)&xlp[kk];
            xl1 = *(const uint4*)&xlp[kk+8];
            wl  = *(const uint4*)&wlp[kk];
        }

        __syncthreads();
        *(uint4*)&XH[fxr*HPSTR + fxc]     = xh0;
        *(uint4*)&XH[fxr*HPSTR + fxc + 8] = xh1;
        *(uint4*)&WH[fwr*HPSTR + fwc]     = wh;
        if (SPLIT) {
            *(uint4*)&XL[fxr*HPSTR + fxc]     = xl0;
            *(uint4*)&XL[fxr*HPSTR + fxc + 8] = xl1;
            *(uint4*)&WL[fwr*HPSTR + fwc]     = wl;
        }
        __syncthreads();

        #pragma unroll
        for (int ks = 0; ks < 2; ks++) {
            uint32_t ah0 = *(uint32_t*)&XH[(qr+gy  )*HPSTR + ks*16 + 2*gx];
            uint32_t ah1 = *(uint32_t*)&XH[(qr+gy+8)*HPSTR + ks*16 + 2*gx];
            uint32_t ah2 = *(uint32_t*)&XH[(qr+gy  )*HPSTR + ks*16 + 2*gx + 8];
            uint32_t ah3 = *(uint32_t*)&XH[(qr+gy+8)*HPSTR + ks*16 + 2*gx + 8];
            uint32_t al0=0, al1=0, al2=0, al3=0;
            if (SPLIT) {
                al0 = *(uint32_t*)&XL[(qr+gy  )*HPSTR + ks*16 + 2*gx];
                al1 = *(uint32_t*)&XL[(qr+gy+8)*HPSTR + ks*16 + 2*gx];
                al2 = *(uint32_t*)&XL[(qr+gy  )*HPSTR + ks*16 + 2*gx + 8];
                al3 = *(uint32_t*)&XL[(qr+gy+8)*HPSTR + ks*16 + 2*gx + 8];
            }
            #pragma unroll
            for (int nt = 0; nt < 8; nt++) {
                uint32_t bh0 = *(uint32_t*)&WH[(nt*8+gy)*HPSTR + ks*16 + 2*gx];
                uint32_t bh1 = *(uint32_t*)&WH[(nt*8+gy)*HPSTR + ks*16 + 2*gx + 8];
                mma_f16(acc1[nt], ah0, ah1, ah2, ah3, bh0, bh1);
                if (SPLIT) {
                    uint32_t bl0 = *(uint32_t*)&WL[(nt*8+gy)*HPSTR + ks*16 + 2*gx];
                    uint32_t bl1 = *(uint32_t*)&WL[(nt*8+gy)*HPSTR + ks*16 + 2*gx + 8];
                    mma_f16(acc2[nt], ah0, ah1, ah2, ah3, bl0, bl1);
                    mma_f16(acc2[nt], al0, al1, al2, al3, bh0, bh1);
                }
            }
        }
    }

    const int hh = blockIdx.x;
    const int m_0 = m0 + qr + gy;
    const int m_1 = m_0 + 8;
    const int b0_ = m_0 >> 11, l0_ = m_0 & (L-1);
    const int b1_ = m_1 >> 11, l1_ = m_1 & (L-1);
    __half* o0 = &out[(((size_t)(b0_*H + hh)*L + l0_)*DH)];
    __half* o1 = &out[(((size_t)(b1_*H + hh)*L + l1_)*DH)];

    const float inv2048 = 1.0f/2048.0f;
    float dot0 = 0.f, n20 = 0.f, dot1 = 0.f, n21 = 0.f;
    #pragma unroll
    for (int nt = 0; nt < 8; nt++) {
        float bs0 = bias[hh*64 + nt*8 + 2*gx];
        float bs1 = bias[hh*64 + nt*8 + 2*gx + 1];
        float v00, v01, v10, v11;
        if (SPLIT) {
            v00 = fmaf(acc2[nt][0], inv2048, acc1[nt][0]) + bs0;
            v01 = fmaf(acc2[nt][1], inv2048, acc1[nt][1]) + bs1;
            v10 = fmaf(acc2[nt][2], inv2048, acc1[nt][2]) + bs0;
            v11 = fmaf(acc2[nt][3], inv2048, acc1[nt][3]) + bs1;
        } else {
            v00 = acc1[nt][0] + bs0; v01 = acc1[nt][1] + bs1;
            v10 = acc1[nt][2] + bs0; v11 = acc1[nt][3] + bs1;
        }
        *(uint32_t*)&o0[nt*8 + 2*gx] = f22h2(v00, v01);
        *(uint32_t*)&o1[nt*8 + 2*gx] = f22h2(v10, v11);
        if (SPLIT) {
            float a0 = ha[nt*8 + 2*gx], a1 = ha[nt*8 + 2*gx + 1];
            dot0 = fmaf(v00, a0, fmaf(v01, a1, dot0));
            dot1 = fmaf(v10, a0, fmaf(v11, a1, dot1));
            n20  = fmaf(v00, v00, fmaf(v01, v01, n20));
            n21  = fmaf(v10, v10, fmaf(v11, v11, n21));
        }
    }
    if (SPLIT) {
        #pragma unroll
        for (int o = 1; o <= 2; o <<= 1) {
            dot0 += __shfl_xor_sync(0xffffffffu, dot0, o);
            dot1 += __shfl_xor_sync(0xffffffffu, dot1, o);
            n20  += __shfl_xor_sync(0xffffffffu, n20, o);
            n21  += __shfl_xor_sync(0xffffffffu, n21, o);
        }
        if (gx == 0) {
            size_t gw0 = (size_t)(b0_*H + hh)*L + l0_;
            size_t gw1 = (size_t)(b1_*H + hh)*L + l1_;
            g_dot[gw0] = dot0; g_norm2[gw0] = n20;
            g_dot[gw1] = dot1; g_norm2[gw1] = n21;
            atomicMax(&g_maxn2[b0_*H + hh], __float_as_uint(n20));
            atomicMax(&g_maxn2[b1_*H + hh], __float_as_uint(n21));
        }
    }
}

// ---------------- hash ----------------
__global__ void hash2_kernel(const float* __restrict__ ha) {
    int t = blockIdx.x * blockDim.x + threadIdx.x;
    if (t >= BH*L) return;
    float dot = g_dot[t], n2 = g_norm2[t];
    float maxn = sqrtf(__uint_as_float(g_maxn2[t >> 11]));
    float s = 0.75f / fmaxf(maxn, 1e-12f);
    float nk2 = s*s*n2;
    float hkval = s*dot + (0.5f - nk2)*ha[DH] + (0.5f - nk2*nk2)*ha[DH+1];
    g_hq[t] = (dot   >= 0.0f) ? 1 : 0;
    g_hk[t] = (hkval >= 0.0f) ? 1 : 0;
}

// ============ fp16 flash attention: P in registers, base-2 softmax ============
#define HSTR 72

#define QS_OFF 0
#define KS_OFF (128*HSTR)
#define VT_OFF (KS_OFF + 64*HSTR)
#define HK_OFF (VT_OFF + 64*HSTR)        // 18432 halves (4B aligned)
#define ASM_HALVES (HK_OFF + 128)
#define ASM_BYTES (ASM_HALVES*2)         // 37376

// scale*log2e and NEG*log2e (base-2 softmax domain)
#define C_SCL 0.1803368801111713f        // 0.125 * log2(e)
#define C_NEG 14426.950408889634f        // 1e4 * log2(e)

__global__ __launch_bounds__(256, 2)
void attn_kernel(float* __restrict__ out) {
    extern __shared__ __half smh[];
    __half* Qs = smh + QS_OFF;
    __half* Ks = smh + KS_OFF;
    __half* Vt = smh + VT_OFF;
    float* hkf = (float*)(smh + HK_OFF);

    const int bh = blockIdx.y;
    const int q0 = blockIdx.x * 128;
    const int tid = threadIdx.x;
    const int warp = tid >> 5;
    const int lane = tid & 31;
    const int gy = lane >> 2;
    const int gx = lane & 3;
    const int qr = warp * 16;

    // ---- Q fill: straight fp16 copy ----
    {
        int r = tid >> 1, c0 = (tid & 1) * 32;
        const __half* qp = &g_qkh[((size_t)bh*L + q0 + r)*DH + c0];
        #pragma unroll
        for (int c8 = 0; c8 < 4; c8++)
            *(uint4*)&Qs[r*HSTR + c0 + c8*8] = *(const uint4*)&qp[c8*8];
    }

    const float fq0 = (float)g_hq[(size_t)bh*L + q0 + qr + gy];
    const float fq1 = (float)g_hq[(size_t)bh*L + q0 + qr + gy + 8];

    float O[8][4];
    #pragma unroll
    for (int nt=0;nt<8;nt++)
        #pragma unroll
        for (int c=0;c<4;c++) O[nt][c] = 0.0f;
    float m0 = -INFINITY, m1 = -INFINITY, l0 = 0.0f, l1 = 0.0f;

    const int fr = tid >> 2;
    const int fc = (tid & 3) * 16;
    const int vd0 = warp * 8;

    for (int k0 = 0; k0 < L; k0 += 64) {
        uint4 kA, kB;
        {
            const __half* kp = &g_qkh[((size_t)bh*L + k0 + fr)*DH + fc];
            kA = ((const uint4*)kp)[0];
            kB = ((const uint4*)kp)[1];
        }
        uint4 va, vb;
        {
            const __half* vp = &g_vh[((size_t)bh*L + k0 + 2*lane)*DH + vd0];
            va = *(const uint4*)vp;
            vb = *(const uint4*)(vp + DH);
        }
        unsigned char hkb = 0;
        if (tid < 64) hkb = g_hk[(size_t)bh*L + k0 + tid];

        __syncthreads();
        *(uint4*)&Ks[fr*HSTR + fc]     = kA;
        *(uint4*)&Ks[fr*HSTR + fc + 8] = kB;
        {
            const uint32_t* aw = (const uint32_t*)&va;
            const uint32_t* bw = (const uint32_t*)&vb;
            #pragma unroll
            for (int j=0;j<4;j++){
                uint32_t lo = __byte_perm(aw[j], bw[j], 0x5410);
                uint32_t hi = __byte_perm(aw[j], bw[j], 0x7632);
                *(uint32_t*)&Vt[(vd0+2*j  )*HSTR + 2*lane] = lo;
                *(uint32_t*)&Vt[(vd0+2*j+1)*HSTR + 2*lane] = hi;
            }
        }
        if (tid < 64) hkf[tid] = (float)hkb;
        __syncthreads();

        // ---- S = Q @ K^T ----
        float S[8][4];
        #pragma unroll
        for (int nt=0;nt<8;nt++)
            #pragma unroll
            for (int c=0;c<4;c++) S[nt][c] = 0.0f;

        #pragma unroll
        for (int ks = 0; ks < 4; ks++) {
            uint32_t a0 = *(uint32_t*)&Qs[(qr+gy  )*HSTR + ks*16 + 2*gx];
            uint32_t a1 = *(uint32_t*)&Qs[(qr+gy+8)*HSTR + ks*16 + 2*gx];
            uint32_t a2 = *(uint32_t*)&Qs[(qr+gy  )*HSTR + ks*16 + 2*gx + 8];
            uint32_t a3 = *(uint32_t*)&Qs[(qr+gy+8)*HSTR + ks*16 + 2*gx + 8];
            #pragma unroll
            for (int nt = 0; nt < 8; nt++) {
                uint32_t b0 = *(uint32_t*)&Ks[(nt*8+gy)*HSTR + ks*16 + 2*gx];
                uint32_t b1 = *(uint32_t*)&Ks[(nt*8+gy)*HSTR + ks*16 + 2*gx + 8];
                mma_f16(S[nt], a0, a1, a2, a3, b0, b1);
            }
        }

        // ---- mask + scale (base-2 domain); row max ----
        float mx0 = -INFINITY, mx1 = -INFINITY;
        #pragma unroll
        for (int nt = 0; nt < 8; nt++) {
            float fk0 = hkf[nt*8 + 2*gx];
            float fk1 = hkf[nt*8 + 2*gx + 1];
            S[nt][0] = fmaf(S[nt][0], C_SCL, -C_NEG*fabsf(fq0 - fk0));
            S[nt][1] = fmaf(S[nt][1], C_SCL, -C_NEG*fabsf(fq0 - fk1));
            S[nt][2] = fmaf(S[nt][2], C_SCL, -C_NEG*fabsf(fq1 - fk0));
            S[nt][3] = fmaf(S[nt][3], C_SCL, -C_NEG*fabsf(fq1 - fk1));
            mx0 = fmaxf(mx0, fmaxf(S[nt][0], S[nt][1]));
            mx1 = fmaxf(mx1, fmaxf(S[nt][2], S[nt][3]));
        }
        #pragma unroll
        for (int o = 1; o <= 2; o <<= 1) {
            mx0 = fmaxf(mx0, __shfl_xor_sync(0xffffffffu, mx0, o));
            mx1 = fmaxf(mx1, __shfl_xor_sync(0xffffffffu, mx1, o));
        }
        float mn0 = fmaxf(m0, mx0), mn1 = fmaxf(m1, mx1);
        float cr0 = ex2f(m0 - mn0), cr1 = ex2f(m1 - mn1);
        m0 = mn0; m1 = mn1;

        // ---- exp2, row sums; pack P directly into A-fragments ----
        uint32_t ph0[8], ph1[8];
        float s0 = 0.0f, s1 = 0.0f;
        #pragma unroll
        for (int nt = 0; nt < 8; nt++) {
            float p0 = ex2f(S[nt][0] - mn0);
            float p1 = ex2f(S[nt][1] - mn0);
            float p2 = ex2f(S[nt][2] - mn1);
            float p3 = ex2f(S[nt][3] - mn1);
            s0 += p0 + p1; s1 += p2 + p3;
            ph0[nt] = f22h2(p0, p1);
            ph1[nt] = f22h2(p2, p3);
        }
        #pragma unroll
        for (int o = 1; o <= 2; o <<= 1) {
            s0 += __shfl_xor_sync(0xffffffffu, s0, o);
            s1 += __shfl_xor_sync(0xffffffffu, s1, o);
        }
        l0 = l0*cr0 + s0;
        l1 = l1*cr1 + s1;

        #pragma unroll
        for (int nt = 0; nt < 8; nt++) {
            O[nt][0] *= cr0; O[nt][1] *= cr0;
            O[nt][2] *= cr1; O[nt][3] *= cr1;
        }

        // ---- O += P @ V (P from registers) ----
        #pragma unroll
        for (int ks = 0; ks < 4; ks++) {
            uint32_t a0 = ph0[2*ks];
            uint32_t a1 = ph1[2*ks];
            uint32_t a2 = ph0[2*ks+1];
            uint32_t a3 = ph1[2*ks+1];
            #pragma unroll
            for (int nt = 0; nt < 8; nt++) {
                uint32_t b0 = *(uint32_t*)&Vt[(nt*8+gy)*HSTR + ks*16 + 2*gx];
                uint32_t b1 = *(uint32_t*)&Vt[(nt*8+gy)*HSTR + ks*16 + 2*gx + 8];
                mma_f16(O[nt], a0, a1, a2, a3, b0, b1);
            }
        }
    }

    const int bb = bh >> 4, hh = bh & 15;
    const float inv0 = 1.0f / l0, inv1 = 1.0f / l1;
    const int l_0 = q0 + qr + gy, l_1 = l_0 + 8;
    float* o0 = &out[((size_t)bb*L + l_0)*DIMM + hh*DH];
    float* o1 = &out[((size_t)bb*L + l_1)*DIMM + hh*DH];
    #pragma unroll
    for (int nt = 0; nt < 8; nt++) {
        *(float2*)&o0[nt*8 + 2*gx] = make_float2(O[nt][0]*inv0, O[nt][1]*inv0);
        *(float2*)&o1[nt*8 + 2*gx] = make_float2(O[nt][2]*inv1, O[nt][3]*inv1);
    }
}

// ---------------- launch ----------------
extern "C" void kernel_launch(void* const* d_in, const int* in_sizes, int n_in,
                              void* d_out, int out_size) {
    const float* X  = (const float*)d_in[0];
    const float* Wq = (const float*)d_in[1];
    const float* bq = (const float*)d_in[2];
    const float* Wv = (const float*)d_in[3];
    const float* bv = (const float*)d_in[4];
    const float* ha = (const float*)d_in[5];
    float* out = (float*)d_out;

    cudaFuncSetAttribute(proj_h_kernel, cudaFuncAttributeMaxDynamicSharedMemorySize, PROJ_SM_BYTES);
    cudaFuncSetAttribute(attn_kernel,   cudaFuncAttributeMaxDynamicSharedMemorySize, ASM_BYTES);

    __half *xh, *xl, *wqh, *wql, *wvh;
    cudaGetSymbolAddress((void**)&xh,  g_XH);
    cudaGetSymbolAddress((void**)&xl,  g_XL);
    cudaGetSymbolAddress((void**)&wqh, g_WqH);
    cudaGetSymbolAddress((void**)&wql, g_WqL);
    cudaGetSymbolAddress((void**)&wvh, g_WvH);
    cvt_kernel<<<(TOK*DIMM/4)/256, 256>>>(X,  xh,  xl,  TOK*DIMM/4, 1);
    cvt_kernel<<<(DIMM*DIMM/4)/256, 256>>>(Wq, wqh, wql, DIMM*DIMM/4, 1);
    cvt_kernel<<<(DIMM*DIMM/4)/256, 256>>>(Wv, wvh, wvh, DIMM*DIMM/4, 0);

    dim3 pg(DIMM/64, TOK/128, 2);
    proj_h_kernel<<<pg, 256, PROJ_SM_BYTES>>>(bq, bv, ha);

    hash2_kernel<<<(BH*L)/256, 256>>>(ha);

    dim3 ag(L/128, BH);
    attn_kernel<<<ag, 256, ASM_BYTES>>>(out);
}